// round 2
// baseline (speedup 1.0000x reference)
#include <cuda_runtime.h>
#include <cuda_bf16.h>

// ---------------- Problem constants ----------------
#define NB      64          // batch (graphs)
#define NNODES  512         // nodes per graph
#define NV      64          // virtual nodes
#define HD      256         // hidden dim
#define IN_DIM  128
#define OUT_DIM 10
#define TOTAL_N (NB * NNODES)        // 32768
#define EDGES   (NB * 16384)         // 1048576

// ---------------- Scratch (static device globals; no allocation) ----------------
__device__ float g_deg[TOTAL_N];
__device__ float g_adj[(long)NB * NNODES * NNODES];   // 67MB dense adjacency
__device__ float g_hemb[(long)TOTAL_N * HD];
__device__ float g_hw[(long)TOTAL_N * HD];
__device__ float g_g[(long)TOTAL_N * HD];             // GCN output (node feats)
__device__ float g_t1[(long)TOTAL_N * HD];
__device__ float g_t[(long)TOTAL_N * HD];
__device__ float g_proto[NB * HD];
__device__ float g_pn[NB];
__device__ float g_att[TOTAL_N];
__device__ float g_c[(long)TOTAL_N * NV];             // normalized mw [B,N,V]
__device__ float g_vn[(long)NB * NV * HD];
__device__ float g_vnr[(long)NB * NV * HD];
__device__ float g_vn2[(long)NB * NV * HD];
__device__ float g_gf[NB * HD];
__device__ float g_m1[NB * HD];

// ---------------- helpers ----------------
__device__ __forceinline__ float warp_sum(float v) {
    #pragma unroll
    for (int o = 16; o > 0; o >>= 1) v += __shfl_xor_sync(0xffffffff, v, o);
    return v;
}

__global__ void zero_kernel(float* __restrict__ p, long n) {
    long i = (long)blockIdx.x * blockDim.x + threadIdx.x;
    if (i < n) p[i] = 0.f;
}

__global__ void deg_init_kernel(float* __restrict__ deg) {
    int i = blockIdx.x * blockDim.x + threadIdx.x;
    if (i < TOTAL_N) deg[i] = 1.0f;   // self-loop
}

__global__ void deg_count_kernel(const int* __restrict__ dst, float* __restrict__ deg) {
    int e = blockIdx.x * blockDim.x + threadIdx.x;
    if (e < EDGES) atomicAdd(&deg[dst[e]], 1.0f);
}

__global__ void adj_fill_kernel(const int* __restrict__ src, const int* __restrict__ dst,
                                const float* __restrict__ deg, float* __restrict__ A) {
    int e = blockIdx.x * blockDim.x + threadIdx.x;
    if (e >= EDGES) return;
    int s = src[e], d = dst[e];
    int g  = d >> 9;           // / 512
    int dl = d & 511, sl = s & 511;
    float coef = rsqrtf(deg[s]) * rsqrtf(deg[d]);
    atomicAdd(&A[((long)g * NNODES + dl) * NNODES + sl], coef);
}

__global__ void adj_diag_kernel(const float* __restrict__ deg, float* __restrict__ A) {
    int i = blockIdx.x * blockDim.x + threadIdx.x;
    if (i >= TOTAL_N) return;
    int g = i >> 9, l = i & 511;
    A[((long)g * NNODES + l) * NNODES + l] += 1.0f / deg[i];
}

// ---------------- 128x128x8 SGEMM (row-major, optional batch/bias/relu) ----------------
__global__ __launch_bounds__(256) void sgemm_k(
    const float* __restrict__ A, const float* __restrict__ Bm,
    const float* __restrict__ bias, float* __restrict__ C,
    int M, int Nc, int K, long sA, long sB, long sC, int hasBias, int relu)
{
    constexpr int BM = 128, BN = 128, BK = 8, TM = 8, TN = 8;
    const int cRow = blockIdx.y, cCol = blockIdx.x;
    A  += (long)blockIdx.z * sA + (long)cRow * BM * K;
    Bm += (long)blockIdx.z * sB + cCol * BN;
    C  += (long)blockIdx.z * sC + (long)cRow * BM * Nc + cCol * BN;

    __shared__ float As[BK * BM];
    __shared__ float Bs[BK * BN];

    const int tid = threadIdx.x;
    const int threadRow = tid / (BN / TN);      // 0..15
    const int threadCol = tid % (BN / TN);      // 0..15
    const int innerRowA = tid / (BK / 4);       // 0..127
    const int innerColA = tid % (BK / 4);       // 0..1
    const int innerRowB = tid / (BN / 4);       // 0..7
    const int innerColB = tid % (BN / 4);       // 0..31

    float acc[TM * TN] = {0.f};
    float regM[TM], regN[TN];

    for (int bk = 0; bk < K; bk += BK) {
        float4 a4 = *reinterpret_cast<const float4*>(A + (long)innerRowA * K + innerColA * 4);
        As[(innerColA * 4 + 0) * BM + innerRowA] = a4.x;
        As[(innerColA * 4 + 1) * BM + innerRowA] = a4.y;
        As[(innerColA * 4 + 2) * BM + innerRowA] = a4.z;
        As[(innerColA * 4 + 3) * BM + innerRowA] = a4.w;
        *reinterpret_cast<float4*>(Bs + innerRowB * BN + innerColB * 4) =
            *reinterpret_cast<const float4*>(Bm + (long)innerRowB * Nc + innerColB * 4);
        __syncthreads();
        A += BK; Bm += (long)BK * Nc;
        #pragma unroll
        for (int k = 0; k < BK; k++) {
            #pragma unroll
            for (int i = 0; i < TM; i++) regM[i] = As[k * BM + threadRow * TM + i];
            #pragma unroll
            for (int j = 0; j < TN; j++) regN[j] = Bs[k * BN + threadCol * TN + j];
            #pragma unroll
            for (int i = 0; i < TM; i++)
                #pragma unroll
                for (int j = 0; j < TN; j++)
                    acc[i * TN + j] += regM[i] * regN[j];
        }
        __syncthreads();
    }

    float bv[TN];
    #pragma unroll
    for (int j = 0; j < TN; j++)
        bv[j] = hasBias ? bias[cCol * BN + threadCol * TN + j] : 0.f;
    #pragma unroll
    for (int i = 0; i < TM; i++) {
        #pragma unroll
        for (int j = 0; j < TN; j += 4) {
            float4 o;
            o.x = acc[i * TN + j + 0] + bv[j + 0];
            o.y = acc[i * TN + j + 1] + bv[j + 1];
            o.z = acc[i * TN + j + 2] + bv[j + 2];
            o.w = acc[i * TN + j + 3] + bv[j + 3];
            if (relu) {
                o.x = fmaxf(o.x, 0.f); o.y = fmaxf(o.y, 0.f);
                o.z = fmaxf(o.z, 0.f); o.w = fmaxf(o.w, 0.f);
            }
            *reinterpret_cast<float4*>(C + (long)(threadRow * TM + i) * Nc + threadCol * TN + j) = o;
        }
    }
}

// ---------------- proto = mean over nodes ----------------
__global__ void proto_kernel(const float* __restrict__ t, float* __restrict__ proto) {
    int b = blockIdx.x, h = threadIdx.x;
    const float* tb = t + (long)b * NNODES * HD + h;
    float s = 0.f;
    #pragma unroll 4
    for (int n = 0; n < NNODES; n++) s += tb[(long)n * HD];
    proto[b * HD + h] = s * (1.0f / NNODES);
}

__global__ void pn_kernel(const float* __restrict__ proto, float* __restrict__ pn) {
    int b = blockIdx.x;
    float v = proto[b * HD + threadIdx.x];
    float s = v * v;
    __shared__ float red[8];
    s = warp_sum(s);
    if ((threadIdx.x & 31) == 0) red[threadIdx.x >> 5] = s;
    __syncthreads();
    if (threadIdx.x == 0) {
        float tot = 0.f;
        #pragma unroll
        for (int i = 0; i < 8; i++) tot += red[i];
        pn[b] = fmaxf(sqrtf(tot), 1e-8f);
    }
}

// ---------------- attention per node (1 warp / node) ----------------
__global__ void att_kernel(const float* __restrict__ t, const float* __restrict__ proto,
                           const float* __restrict__ pn, float* __restrict__ att) {
    int warp = (blockIdx.x * blockDim.x + threadIdx.x) >> 5;
    int lane = threadIdx.x & 31;
    if (warp >= TOTAL_N) return;
    int b = warp / NNODES;
    const float* tr = t + (long)warp * HD;
    const float* pr = proto + b * HD;
    float s2 = 0.f, dp = 0.f;
    #pragma unroll
    for (int h = lane; h < HD; h += 32) {
        float tv = tr[h];
        s2 += tv * tv;
        dp += tv * pr[h];
    }
    s2 = warp_sum(s2);
    dp = warp_sum(dp);
    if (lane == 0) {
        float tn  = fmaxf(sqrtf(s2), 1e-8f);
        float sim = dp / (tn * pn[b]);
        att[warp] = 0.5f * (1.0f + sim);
    }
}

// ---------------- mw = row-normalized (ew * att), 1 warp / node ----------------
__global__ void mw_kernel(const float* __restrict__ ew, const float* __restrict__ att,
                          float* __restrict__ c) {
    int warp = (blockIdx.x * blockDim.x + threadIdx.x) >> 5;
    int lane = threadIdx.x & 31;
    if (warp >= TOTAL_N) return;
    float a = att[warp];
    const float* er = ew + (long)warp * NV;
    float m0 = er[lane]      * a;
    float m1 = er[lane + 32] * a;
    float rs = warp_sum(m0 + m1);
    float d  = (rs == 0.f) ? 1.f : rs;
    c[(long)warp * NV + lane]      = m0 / d;
    c[(long)warp * NV + lane + 32] = m1 / d;
}

// ---------------- vn[b,v,h] = sum_n c[b,n,v] * g[b,n,h]  (8 v per block) ----------------
__global__ __launch_bounds__(256) void vn_kernel(const float* __restrict__ c,
                                                 const float* __restrict__ g,
                                                 float* __restrict__ vn) {
    int b = blockIdx.y, v0 = blockIdx.x * 8, h = threadIdx.x;
    __shared__ float sc[NNODES * 8];   // 16KB, layout [n][vi]
    for (int idx = threadIdx.x; idx < NNODES * 8; idx += 256) {
        int n = idx >> 3, vi = idx & 7;
        sc[idx] = c[((long)b * NNODES + n) * NV + v0 + vi];
    }
    __syncthreads();
    const float* gb = g + (long)b * NNODES * HD + h;
    float acc[8] = {0.f};
    for (int n = 0; n < NNODES; n++) {
        float gv = gb[(long)n * HD];
        #pragma unroll
        for (int vi = 0; vi < 8; vi++) acc[vi] += sc[n * 8 + vi] * gv;
    }
    #pragma unroll
    for (int vi = 0; vi < 8; vi++)
        vn[((long)b * NV + v0 + vi) * HD + h] = acc[vi];
}

// ---------------- gf = mean over virtual nodes ----------------
__global__ void gf_kernel(const float* __restrict__ vn2, float* __restrict__ gf) {
    int b = blockIdx.x, h = threadIdx.x;
    float s = 0.f;
    #pragma unroll 4
    for (int v = 0; v < NV; v++) s += vn2[((long)b * NV + v) * HD + h];
    gf[b * HD + h] = s * (1.0f / NV);
}

// ---------------- tiny MLP head ----------------
__global__ void mlp1_kernel(const float* __restrict__ gf, const float* __restrict__ W,
                            const float* __restrict__ bb, float* __restrict__ out) {
    int b = blockIdx.x, h = threadIdx.x;
    __shared__ float sg[HD];
    sg[h] = gf[b * HD + h];
    __syncthreads();
    float acc = 0.f;
    #pragma unroll 4
    for (int k = 0; k < HD; k++) acc += sg[k] * W[k * HD + h];
    out[b * HD + h] = fmaxf(acc + bb[h], 0.f);
}

__global__ void out_kernel(const float* __restrict__ m1, const float* __restrict__ W,
                           const float* __restrict__ bb, float* __restrict__ out) {
    int b = blockIdx.x, tid = threadIdx.x;
    __shared__ float sm[HD];
    sm[tid] = m1[b * HD + tid];
    __syncthreads();
    if (tid < OUT_DIM) {
        float acc = 0.f;
        #pragma unroll 4
        for (int k = 0; k < HD; k++) acc += sm[k] * W[k * OUT_DIM + tid];
        out[b * OUT_DIM + tid] = acc + bb[tid];
    }
}

// ---------------- launch ----------------
extern "C" void kernel_launch(void* const* d_in, const int* in_sizes, int n_in,
                              void* d_out, int out_size) {
    const float* x     = (const float*)d_in[0];
    const int*   esrc  = (const int*)  d_in[1];
    const int*   edst  = (const int*)  d_in[2];
    const float* W_emb = (const float*)d_in[3];
    const float* b_emb = (const float*)d_in[4];
    const float* W_gcn = (const float*)d_in[5];
    const float* b_gcn = (const float*)d_in[6];
    const float* aW1   = (const float*)d_in[7];
    const float* ab1   = (const float*)d_in[8];
    const float* aW2   = (const float*)d_in[9];
    const float* ab2   = (const float*)d_in[10];
    const float* vW1   = (const float*)d_in[11];
    const float* vb1   = (const float*)d_in[12];
    const float* vW2   = (const float*)d_in[13];
    const float* vb2   = (const float*)d_in[14];
    const float* mW1   = (const float*)d_in[15];
    const float* mb1   = (const float*)d_in[16];
    const float* mW2   = (const float*)d_in[17];
    const float* mb2   = (const float*)d_in[18];
    const float* ew    = (const float*)d_in[19];
    float* out = (float*)d_out;

    float *d_deg, *d_adj, *d_hemb, *d_hw, *d_g, *d_t1, *d_t, *d_proto, *d_pn,
          *d_att, *d_c, *d_vn, *d_vnr, *d_vn2, *d_gf, *d_m1;
    cudaGetSymbolAddress((void**)&d_deg,   g_deg);
    cudaGetSymbolAddress((void**)&d_adj,   g_adj);
    cudaGetSymbolAddress((void**)&d_hemb,  g_hemb);
    cudaGetSymbolAddress((void**)&d_hw,    g_hw);
    cudaGetSymbolAddress((void**)&d_g,     g_g);
    cudaGetSymbolAddress((void**)&d_t1,    g_t1);
    cudaGetSymbolAddress((void**)&d_t,     g_t);
    cudaGetSymbolAddress((void**)&d_proto, g_proto);
    cudaGetSymbolAddress((void**)&d_pn,    g_pn);
    cudaGetSymbolAddress((void**)&d_att,   g_att);
    cudaGetSymbolAddress((void**)&d_c,     g_c);
    cudaGetSymbolAddress((void**)&d_vn,    g_vn);
    cudaGetSymbolAddress((void**)&d_vnr,   g_vnr);
    cudaGetSymbolAddress((void**)&d_vn2,   g_vn2);
    cudaGetSymbolAddress((void**)&d_gf,    g_gf);
    cudaGetSymbolAddress((void**)&d_m1,    g_m1);

    const long adjN = (long)NB * NNODES * NNODES;

    // degrees + dense per-graph adjacency (self-loops on the diagonal)
    zero_kernel<<<(unsigned)((adjN + 255) / 256), 256>>>(d_adj, adjN);
    deg_init_kernel<<<TOTAL_N / 256, 256>>>(d_deg);
    deg_count_kernel<<<EDGES / 256, 256>>>(edst, d_deg);

    // node embedding: h = x @ W_emb + b_emb
    sgemm_k<<<dim3(HD / 128, TOTAL_N / 128, 1), 256>>>(
        x, W_emb, b_emb, d_hemb, TOTAL_N, HD, IN_DIM, 0, 0, 0, 1, 0);

    // hw = h @ W_gcn
    sgemm_k<<<dim3(HD / 128, TOTAL_N / 128, 1), 256>>>(
        d_hemb, W_gcn, b_emb, d_hw, TOTAL_N, HD, HD, 0, 0, 0, 0, 0);

    adj_fill_kernel<<<EDGES / 256, 256>>>(esrc, edst, d_deg, d_adj);
    adj_diag_kernel<<<TOTAL_N / 256, 256>>>(d_deg, d_adj);

    // g = relu(A @ hw + b_gcn), batched per graph
    sgemm_k<<<dim3(HD / 128, NNODES / 128, NB), 256>>>(
        d_adj, d_hw, b_gcn, d_g, NNODES, HD, NNODES,
        (long)NNODES * NNODES, (long)NNODES * HD, (long)NNODES * HD, 1, 1);

    // affinity MLP: t = relu(g@aW1+ab1)@aW2+ab2
    sgemm_k<<<dim3(HD / 128, TOTAL_N / 128, 1), 256>>>(
        d_g, aW1, ab1, d_t1, TOTAL_N, HD, HD, 0, 0, 0, 1, 1);
    sgemm_k<<<dim3(HD / 128, TOTAL_N / 128, 1), 256>>>(
        d_t1, aW2, ab2, d_t, TOTAL_N, HD, HD, 0, 0, 0, 1, 0);

    proto_kernel<<<NB, HD>>>(d_t, d_proto);
    pn_kernel<<<NB, HD>>>(d_proto, d_pn);
    att_kernel<<<TOTAL_N / 8, 256>>>(d_t, d_proto, d_pn, d_att);
    mw_kernel<<<TOTAL_N / 8, 256>>>(ew, d_att, d_c);

    // vn = mw^T @ g per graph
    vn_kernel<<<dim3(NV / 8, NB), 256>>>(d_c, d_g, d_vn);

    // virtual-node MLP
    sgemm_k<<<dim3(HD / 128, (NB * NV) / 128, 1), 256>>>(
        d_vn, vW1, vb1, d_vnr, NB * NV, HD, HD, 0, 0, 0, 1, 1);
    sgemm_k<<<dim3(HD / 128, (NB * NV) / 128, 1), 256>>>(
        d_vnr, vW2, vb2, d_vn2, NB * NV, HD, HD, 0, 0, 0, 1, 0);

    gf_kernel<<<NB, HD>>>(d_vn2, d_gf);
    mlp1_kernel<<<NB, HD>>>(d_gf, mW1, mb1, d_m1);
    out_kernel<<<NB, HD>>>(d_m1, mW2, mb2, out);
}

// round 3
// speedup vs baseline: 1.1529x; 1.1529x over previous
#include <cuda_runtime.h>
#include <cuda_bf16.h>

// ---------------- Problem constants ----------------
#define NB      64          // batch (graphs)
#define NNODES  512         // nodes per graph
#define NV      64          // virtual nodes
#define HD      256         // hidden dim
#define IN_DIM  128
#define OUT_DIM 10
#define TOTAL_N (NB * NNODES)        // 32768
#define EDGES   (NB * 16384)         // 1048576
#define CSR_CAP 128                  // per-node edge capacity (17 sigma above mean 32)

// ---------------- Scratch (static device globals; no allocation) ----------------
__device__ float g_deg[TOTAL_N];
__device__ int   g_cnt[TOTAL_N];
__device__ int   g_csr_src[(long)TOTAL_N * CSR_CAP];    // 16MB
__device__ float g_csr_coef[(long)TOTAL_N * CSR_CAP];   // 16MB
__device__ float g_hemb[(long)TOTAL_N * HD];
__device__ float g_hw[(long)TOTAL_N * HD];
__device__ float g_g[(long)TOTAL_N * HD];               // GCN output (node feats)
__device__ float g_t1[(long)TOTAL_N * HD];
__device__ float g_t[(long)TOTAL_N * HD];
__device__ float g_proto[NB * HD];
__device__ float g_pn[NB];
__device__ float g_c[(long)TOTAL_N * NV];               // normalized mw [B,N,V]
__device__ float g_vn[(long)NB * NV * HD];
__device__ float g_vnr[(long)NB * NV * HD];
__device__ float g_vn2[(long)NB * NV * HD];
__device__ float g_gf[NB * HD];
__device__ float g_m1[NB * HD];

// ---------------- helpers ----------------
__device__ __forceinline__ float warp_sum(float v) {
    #pragma unroll
    for (int o = 16; o > 0; o >>= 1) v += __shfl_xor_sync(0xffffffff, v, o);
    return v;
}

__global__ void deg_init_kernel(float* __restrict__ deg, int* __restrict__ cnt) {
    int i = blockIdx.x * blockDim.x + threadIdx.x;
    if (i < TOTAL_N) { deg[i] = 1.0f; cnt[i] = 0; }   // self-loop in deg
}

__global__ void deg_count_kernel(const int* __restrict__ dst, float* __restrict__ deg) {
    int e = blockIdx.x * blockDim.x + threadIdx.x;
    if (e < EDGES) atomicAdd(&deg[dst[e]], 1.0f);
}

// fixed-stride CSR build (keeps duplicate edges, order irrelevant)
__global__ void csr_fill_kernel(const int* __restrict__ src, const int* __restrict__ dst,
                                const float* __restrict__ deg,
                                int* __restrict__ cnt,
                                int* __restrict__ csr_src, float* __restrict__ csr_coef) {
    int e = blockIdx.x * blockDim.x + threadIdx.x;
    if (e >= EDGES) return;
    int s = src[e], d = dst[e];
    int pos = atomicAdd(&cnt[d], 1);
    if (pos < CSR_CAP) {
        long slot = (long)d * CSR_CAP + pos;
        csr_src[slot]  = s;
        csr_coef[slot] = rsqrtf(deg[s]) * rsqrtf(deg[d]);
    }
}

// g[d,h] = relu( sum_e coef_e * hw[src_e,h] + hw[d,h]/deg[d] + b_gcn[h] )
// one block per node, one thread per feature
__global__ __launch_bounds__(256) void gcn_gather_kernel(
    const int* __restrict__ cnt, const int* __restrict__ csr_src,
    const float* __restrict__ csr_coef, const float* __restrict__ deg,
    const float* __restrict__ hw, const float* __restrict__ bias,
    float* __restrict__ g)
{
    int node = blockIdx.x;
    int h = threadIdx.x;
    int m = cnt[node]; if (m > CSR_CAP) m = CSR_CAP;
    long base = (long)node * CSR_CAP;

    float acc = hw[(long)node * HD + h] * (1.0f / deg[node]);   // self-loop term

    int e = 0;
    for (; e + 4 <= m; e += 4) {
        int   s0 = csr_src[base + e + 0], s1 = csr_src[base + e + 1];
        int   s2 = csr_src[base + e + 2], s3 = csr_src[base + e + 3];
        float c0 = csr_coef[base + e + 0], c1 = csr_coef[base + e + 1];
        float c2 = csr_coef[base + e + 2], c3 = csr_coef[base + e + 3];
        float v0 = hw[(long)s0 * HD + h];
        float v1 = hw[(long)s1 * HD + h];
        float v2 = hw[(long)s2 * HD + h];
        float v3 = hw[(long)s3 * HD + h];
        acc += c0 * v0 + c1 * v1 + c2 * v2 + c3 * v3;
    }
    for (; e < m; e++) {
        int   s0 = csr_src[base + e];
        float c0 = csr_coef[base + e];
        acc += c0 * hw[(long)s0 * HD + h];
    }
    g[(long)node * HD + h] = fmaxf(acc + bias[h], 0.0f);
}

// ---------------- 128x128x8 SGEMM (row-major, optional bias/relu) ----------------
__global__ __launch_bounds__(256) void sgemm_k(
    const float* __restrict__ A, const float* __restrict__ Bm,
    const float* __restrict__ bias, float* __restrict__ C,
    int M, int Nc, int K, int hasBias, int relu)
{
    constexpr int BM = 128, BN = 128, BK = 8, TM = 8, TN = 8;
    const int cRow = blockIdx.y, cCol = blockIdx.x;
    A  += (long)cRow * BM * K;
    Bm += cCol * BN;
    C  += (long)cRow * BM * Nc + cCol * BN;

    __shared__ float As[BK * BM];
    __shared__ float Bs[BK * BN];

    const int tid = threadIdx.x;
    const int threadRow = tid / (BN / TN);
    const int threadCol = tid % (BN / TN);
    const int innerRowA = tid / (BK / 4);
    const int innerColA = tid % (BK / 4);
    const int innerRowB = tid / (BN / 4);
    const int innerColB = tid % (BN / 4);

    float acc[TM * TN] = {0.f};
    float regM[TM], regN[TN];

    for (int bk = 0; bk < K; bk += BK) {
        float4 a4 = *reinterpret_cast<const float4*>(A + (long)innerRowA * K + innerColA * 4);
        As[(innerColA * 4 + 0) * BM + innerRowA] = a4.x;
        As[(innerColA * 4 + 1) * BM + innerRowA] = a4.y;
        As[(innerColA * 4 + 2) * BM + innerRowA] = a4.z;
        As[(innerColA * 4 + 3) * BM + innerRowA] = a4.w;
        *reinterpret_cast<float4*>(Bs + innerRowB * BN + innerColB * 4) =
            *reinterpret_cast<const float4*>(Bm + (long)innerRowB * Nc + innerColB * 4);
        __syncthreads();
        A += BK; Bm += (long)BK * Nc;
        #pragma unroll
        for (int k = 0; k < BK; k++) {
            #pragma unroll
            for (int i = 0; i < TM; i++) regM[i] = As[k * BM + threadRow * TM + i];
            #pragma unroll
            for (int j = 0; j < TN; j++) regN[j] = Bs[k * BN + threadCol * TN + j];
            #pragma unroll
            for (int i = 0; i < TM; i++)
                #pragma unroll
                for (int j = 0; j < TN; j++)
                    acc[i * TN + j] += regM[i] * regN[j];
        }
        __syncthreads();
    }

    float bv[TN];
    #pragma unroll
    for (int j = 0; j < TN; j++)
        bv[j] = hasBias ? bias[cCol * BN + threadCol * TN + j] : 0.f;
    #pragma unroll
    for (int i = 0; i < TM; i++) {
        #pragma unroll
        for (int j = 0; j < TN; j += 4) {
            float4 o;
            o.x = acc[i * TN + j + 0] + bv[j + 0];
            o.y = acc[i * TN + j + 1] + bv[j + 1];
            o.z = acc[i * TN + j + 2] + bv[j + 2];
            o.w = acc[i * TN + j + 3] + bv[j + 3];
            if (relu) {
                o.x = fmaxf(o.x, 0.f); o.y = fmaxf(o.y, 0.f);
                o.z = fmaxf(o.z, 0.f); o.w = fmaxf(o.w, 0.f);
            }
            *reinterpret_cast<float4*>(C + (long)(threadRow * TM + i) * Nc + threadCol * TN + j) = o;
        }
    }
}

// ---------------- proto = mean over nodes, + its norm (fused) ----------------
__global__ void proto_pn_kernel(const float* __restrict__ t, float* __restrict__ proto,
                                float* __restrict__ pn) {
    int b = blockIdx.x, h = threadIdx.x;
    const float* tb = t + (long)b * NNODES * HD + h;
    float s = 0.f;
    #pragma unroll 4
    for (int n = 0; n < NNODES; n++) s += tb[(long)n * HD];
    float p = s * (1.0f / NNODES);
    proto[b * HD + h] = p;

    __shared__ float red[8];
    float sq = warp_sum(p * p);
    if ((h & 31) == 0) red[h >> 5] = sq;
    __syncthreads();
    if (h == 0) {
        float tot = 0.f;
        #pragma unroll
        for (int i = 0; i < 8; i++) tot += red[i];
        pn[b] = fmaxf(sqrtf(tot), 1e-8f);
    }
}

// ---------------- fused attention + row-normalized mw (1 warp / node) ----------------
__global__ void att_mw_kernel(const float* __restrict__ t, const float* __restrict__ proto,
                              const float* __restrict__ pn, const float* __restrict__ ew,
                              float* __restrict__ c) {
    int warp = (blockIdx.x * blockDim.x + threadIdx.x) >> 5;
    int lane = threadIdx.x & 31;
    if (warp >= TOTAL_N) return;
    int b = warp >> 9;
    const float* tr = t + (long)warp * HD;
    const float* pr = proto + b * HD;
    float s2 = 0.f, dp = 0.f;
    #pragma unroll
    for (int h = lane; h < HD; h += 32) {
        float tv = tr[h];
        s2 += tv * tv;
        dp += tv * pr[h];
    }
    s2 = warp_sum(s2);
    dp = warp_sum(dp);
    float tn  = fmaxf(sqrtf(s2), 1e-8f);
    float a   = 0.5f * (1.0f + dp / (tn * pn[b]));   // same in all lanes

    const float* er = ew + (long)warp * NV;
    float m0 = er[lane]      * a;
    float m1 = er[lane + 32] * a;
    float rs = warp_sum(m0 + m1);
    float d  = (rs == 0.f) ? 1.f : rs;
    c[(long)warp * NV + lane]      = m0 / d;
    c[(long)warp * NV + lane + 32] = m1 / d;
}

// ---------------- vn[b,v,h] = sum_n c[b,n,v] * g[b,n,h]  (8 v per block) ----------------
__global__ __launch_bounds__(256) void vn_kernel(const float* __restrict__ c,
                                                 const float* __restrict__ g,
                                                 float* __restrict__ vn) {
    int b = blockIdx.y, v0 = blockIdx.x * 8, h = threadIdx.x;
    __shared__ float sc[NNODES * 8];   // 16KB, layout [n][vi]
    for (int idx = threadIdx.x; idx < NNODES * 8; idx += 256) {
        int n = idx >> 3, vi = idx & 7;
        sc[idx] = c[((long)b * NNODES + n) * NV + v0 + vi];
    }
    __syncthreads();
    const float* gb = g + (long)b * NNODES * HD + h;
    float acc[8] = {0.f};
    for (int n = 0; n < NNODES; n++) {
        float gv = gb[(long)n * HD];
        #pragma unroll
        for (int vi = 0; vi < 8; vi++) acc[vi] += sc[n * 8 + vi] * gv;
    }
    #pragma unroll
    for (int vi = 0; vi < 8; vi++)
        vn[((long)b * NV + v0 + vi) * HD + h] = acc[vi];
}

// ---------------- gf = mean over virtual nodes ----------------
__global__ void gf_kernel(const float* __restrict__ vn2, float* __restrict__ gf) {
    int b = blockIdx.x, h = threadIdx.x;
    float s = 0.f;
    #pragma unroll 4
    for (int v = 0; v < NV; v++) s += vn2[((long)b * NV + v) * HD + h];
    gf[b * HD + h] = s * (1.0f / NV);
}

// ---------------- tiny MLP head ----------------
__global__ void mlp1_kernel(const float* __restrict__ gf, const float* __restrict__ W,
                            const float* __restrict__ bb, float* __restrict__ out) {
    int b = blockIdx.x, h = threadIdx.x;
    __shared__ float sg[HD];
    sg[h] = gf[b * HD + h];
    __syncthreads();
    float acc = 0.f;
    #pragma unroll 4
    for (int k = 0; k < HD; k++) acc += sg[k] * W[k * HD + h];
    out[b * HD + h] = fmaxf(acc + bb[h], 0.f);
}

__global__ void out_kernel(const float* __restrict__ m1, const float* __restrict__ W,
                           const float* __restrict__ bb, float* __restrict__ out) {
    int b = blockIdx.x, tid = threadIdx.x;
    __shared__ float sm[HD];
    sm[tid] = m1[b * HD + tid];
    __syncthreads();
    if (tid < OUT_DIM) {
        float acc = 0.f;
        #pragma unroll 4
        for (int k = 0; k < HD; k++) acc += sm[k] * W[k * OUT_DIM + tid];
        out[b * OUT_DIM + tid] = acc + bb[tid];
    }
}

// ---------------- launch ----------------
extern "C" void kernel_launch(void* const* d_in, const int* in_sizes, int n_in,
                              void* d_out, int out_size) {
    const float* x     = (const float*)d_in[0];
    const int*   esrc  = (const int*)  d_in[1];
    const int*   edst  = (const int*)  d_in[2];
    const float* W_emb = (const float*)d_in[3];
    const float* b_emb = (const float*)d_in[4];
    const float* W_gcn = (const float*)d_in[5];
    const float* b_gcn = (const float*)d_in[6];
    const float* aW1   = (const float*)d_in[7];
    const float* ab1   = (const float*)d_in[8];
    const float* aW2   = (const float*)d_in[9];
    const float* ab2   = (const float*)d_in[10];
    const float* vW1   = (const float*)d_in[11];
    const float* vb1   = (const float*)d_in[12];
    const float* vW2   = (const float*)d_in[13];
    const float* vb2   = (const float*)d_in[14];
    const float* mW1   = (const float*)d_in[15];
    const float* mb1   = (const float*)d_in[16];
    const float* mW2   = (const float*)d_in[17];
    const float* mb2   = (const float*)d_in[18];
    const float* ew    = (const float*)d_in[19];
    float* out = (float*)d_out;

    float *d_deg, *d_csr_coef, *d_hemb, *d_hw, *d_g, *d_t1, *d_t, *d_proto, *d_pn,
          *d_c, *d_vn, *d_vnr, *d_vn2, *d_gf, *d_m1;
    int *d_cnt, *d_csr_src;
    cudaGetSymbolAddress((void**)&d_deg,      g_deg);
    cudaGetSymbolAddress((void**)&d_cnt,      g_cnt);
    cudaGetSymbolAddress((void**)&d_csr_src,  g_csr_src);
    cudaGetSymbolAddress((void**)&d_csr_coef, g_csr_coef);
    cudaGetSymbolAddress((void**)&d_hemb,     g_hemb);
    cudaGetSymbolAddress((void**)&d_hw,       g_hw);
    cudaGetSymbolAddress((void**)&d_g,        g_g);
    cudaGetSymbolAddress((void**)&d_t1,       g_t1);
    cudaGetSymbolAddress((void**)&d_t,        g_t);
    cudaGetSymbolAddress((void**)&d_proto,    g_proto);
    cudaGetSymbolAddress((void**)&d_pn,       g_pn);
    cudaGetSymbolAddress((void**)&d_c,        g_c);
    cudaGetSymbolAddress((void**)&d_vn,       g_vn);
    cudaGetSymbolAddress((void**)&d_vnr,      g_vnr);
    cudaGetSymbolAddress((void**)&d_vn2,      g_vn2);
    cudaGetSymbolAddress((void**)&d_gf,       g_gf);
    cudaGetSymbolAddress((void**)&d_m1,       g_m1);

    // degrees + fixed-stride CSR
    deg_init_kernel<<<TOTAL_N / 256, 256>>>(d_deg, d_cnt);
    deg_count_kernel<<<EDGES / 256, 256>>>(edst, d_deg);
    csr_fill_kernel<<<EDGES / 256, 256>>>(esrc, edst, d_deg, d_cnt, d_csr_src, d_csr_coef);

    // node embedding: h = x @ W_emb + b_emb
    sgemm_k<<<dim3(HD / 128, TOTAL_N / 128), 256>>>(
        x, W_emb, b_emb, d_hemb, TOTAL_N, HD, IN_DIM, 1, 0);

    // hw = h @ W_gcn
    sgemm_k<<<dim3(HD / 128, TOTAL_N / 128), 256>>>(
        d_hemb, W_gcn, b_emb, d_hw, TOTAL_N, HD, HD, 0, 0);

    // g = relu(gather(A, hw) + b_gcn) via CSR (sparse aggregation)
    gcn_gather_kernel<<<TOTAL_N, 256>>>(d_cnt, d_csr_src, d_csr_coef, d_deg,
                                        d_hw, b_gcn, d_g);

    // affinity MLP: t = relu(g@aW1+ab1)@aW2+ab2
    sgemm_k<<<dim3(HD / 128, TOTAL_N / 128), 256>>>(
        d_g, aW1, ab1, d_t1, TOTAL_N, HD, HD, 1, 1);
    sgemm_k<<<dim3(HD / 128, TOTAL_N / 128), 256>>>(
        d_t1, aW2, ab2, d_t, TOTAL_N, HD, HD, 1, 0);

    proto_pn_kernel<<<NB, HD>>>(d_t, d_proto, d_pn);
    att_mw_kernel<<<TOTAL_N / 8, 256>>>(d_t, d_proto, d_pn, ew, d_c);

    // vn = mw^T @ g per graph
    vn_kernel<<<dim3(NV / 8, NB), 256>>>(d_c, d_g, d_vn);

    // virtual-node MLP
    sgemm_k<<<dim3(HD / 128, (NB * NV) / 128), 256>>>(
        d_vn, vW1, vb1, d_vnr, NB * NV, HD, HD, 1, 1);
    sgemm_k<<<dim3(HD / 128, (NB * NV) / 128), 256>>>(
        d_vnr, vW2, vb2, d_vn2, NB * NV, HD, HD, 1, 0);

    gf_kernel<<<NB, HD>>>(d_vn2, d_gf);
    mlp1_kernel<<<NB, HD>>>(d_gf, mW1, mb1, d_m1);
    out_kernel<<<NB, HD>>>(d_m1, mW2, mb2, out);
}

// round 5
// speedup vs baseline: 1.4862x; 1.2891x over previous
#include <cuda_runtime.h>
#include <cuda_bf16.h>
#include <cstdint>

// ---------------- Problem constants ----------------
#define NB      64
#define NNODES  512
#define NV      64
#define HD      256
#define IN_DIM  128
#define OUT_DIM 10
#define TOTAL_N (NB * NNODES)        // 32768
#define EDGES   (NB * 16384)         // 1048576
#define CSR_CAP 128

// ---------------- Scratch ----------------
__device__ float g_deg[TOTAL_N];
__device__ int   g_cnt[TOTAL_N];
__device__ int2  g_csr[(long)TOTAL_N * CSR_CAP];
__device__ float g_wc[IN_DIM * HD];
__device__ float g_bc[HD];
__device__ float g_hw[(long)TOTAL_N * HD];
__device__ float g_g[(long)TOTAL_N * HD];
__device__ float g_t1[(long)TOTAL_N * HD];
__device__ float g_t[(long)TOTAL_N * HD];
__device__ float g_proto[NB * HD];
__device__ float g_pn[NB];
__device__ float g_c[(long)TOTAL_N * NV];
__device__ float g_vn[(long)NB * NV * HD];
__device__ float g_vnr[(long)NB * NV * HD];
__device__ float g_vn2[(long)NB * NV * HD];
__device__ float g_gf[NB * HD];
__device__ float g_m1[NB * HD];

// ---------------- helpers ----------------
__device__ __forceinline__ float warp_sum(float v) {
    #pragma unroll
    for (int o = 16; o > 0; o >>= 1) v += __shfl_xor_sync(0xffffffff, v, o);
    return v;
}

__global__ void deg_init_kernel(float* __restrict__ deg, int* __restrict__ cnt) {
    int i = blockIdx.x * blockDim.x + threadIdx.x;
    if (i < TOTAL_N) { deg[i] = 1.0f; cnt[i] = 0; }
}

__global__ void deg_count_kernel(const int* __restrict__ dst, float* __restrict__ deg) {
    int e = blockIdx.x * blockDim.x + threadIdx.x;
    if (e < EDGES) atomicAdd(&deg[dst[e]], 1.0f);
}

__global__ void csr_fill_kernel(const int* __restrict__ src, const int* __restrict__ dst,
                                const float* __restrict__ deg,
                                int* __restrict__ cnt, int2* __restrict__ csr) {
    int e = blockIdx.x * blockDim.x + threadIdx.x;
    if (e >= EDGES) return;
    int s = src[e], d = dst[e];
    int pos = atomicAdd(&cnt[d], 1);
    if (pos < CSR_CAP) {
        float coef = rsqrtf(deg[s]) * rsqrtf(deg[d]);
        csr[(long)d * CSR_CAP + pos] = make_int2(s, __float_as_int(coef));
    }
}

// ---------------- fp32 SGEMM (tiny weight fold only) ----------------
__global__ __launch_bounds__(256) void sgemm_k(
    const float* __restrict__ A, const float* __restrict__ Bm,
    float* __restrict__ C, int M, int Nc, int K)
{
    constexpr int BM = 128, BN = 128, BK = 8, TM = 8, TN = 8;
    const int cRow = blockIdx.y, cCol = blockIdx.x;
    A  += (long)cRow * BM * K;
    Bm += cCol * BN;
    C  += (long)cRow * BM * Nc + cCol * BN;
    __shared__ float As[BK * BM];
    __shared__ float Bs[BK * BN];
    const int tid = threadIdx.x;
    const int threadRow = tid / (BN / TN);
    const int threadCol = tid % (BN / TN);
    const int innerRowA = tid / (BK / 4);
    const int innerColA = tid % (BK / 4);
    const int innerRowB = tid / (BN / 4);
    const int innerColB = tid % (BN / 4);
    float acc[TM * TN] = {0.f};
    float regM[TM], regN[TN];
    for (int bk = 0; bk < K; bk += BK) {
        float4 a4 = *reinterpret_cast<const float4*>(A + (long)innerRowA * K + innerColA * 4);
        As[(innerColA * 4 + 0) * BM + innerRowA] = a4.x;
        As[(innerColA * 4 + 1) * BM + innerRowA] = a4.y;
        As[(innerColA * 4 + 2) * BM + innerRowA] = a4.z;
        As[(innerColA * 4 + 3) * BM + innerRowA] = a4.w;
        *reinterpret_cast<float4*>(Bs + innerRowB * BN + innerColB * 4) =
            *reinterpret_cast<const float4*>(Bm + (long)innerRowB * Nc + innerColB * 4);
        __syncthreads();
        A += BK; Bm += (long)BK * Nc;
        #pragma unroll
        for (int k = 0; k < BK; k++) {
            #pragma unroll
            for (int i = 0; i < TM; i++) regM[i] = As[k * BM + threadRow * TM + i];
            #pragma unroll
            for (int j = 0; j < TN; j++) regN[j] = Bs[k * BN + threadCol * TN + j];
            #pragma unroll
            for (int i = 0; i < TM; i++)
                #pragma unroll
                for (int j = 0; j < TN; j++)
                    acc[i * TN + j] += regM[i] * regN[j];
        }
        __syncthreads();
    }
    #pragma unroll
    for (int i = 0; i < TM; i++)
        #pragma unroll
        for (int j = 0; j < TN; j += 4) {
            float4 o;
            o.x = acc[i * TN + j + 0]; o.y = acc[i * TN + j + 1];
            o.z = acc[i * TN + j + 2]; o.w = acc[i * TN + j + 3];
            *reinterpret_cast<float4*>(C + (long)(threadRow * TM + i) * Nc + threadCol * TN + j) = o;
        }
}

__global__ void bias_combine_kernel(const float* __restrict__ b_emb,
                                    const float* __restrict__ Wg,
                                    float* __restrict__ bc) {
    int j = threadIdx.x;
    float s = 0.f;
    #pragma unroll 4
    for (int k = 0; k < HD; k++) s += b_emb[k] * Wg[k * HD + j];
    bc[j] = s;
}

// ---------------- 3xTF32 tensor-core GEMM (fp32-accurate) ----------------
__device__ __forceinline__ void mma_tf32(float* d, const uint32_t* a, const uint32_t* b) {
    asm volatile(
        "mma.sync.aligned.m16n8k8.row.col.f32.tf32.tf32.f32 "
        "{%0,%1,%2,%3}, {%4,%5,%6,%7}, {%8,%9}, {%0,%1,%2,%3};\n"
        : "+f"(d[0]), "+f"(d[1]), "+f"(d[2]), "+f"(d[3])
        : "r"(a[0]), "r"(a[1]), "r"(a[2]), "r"(a[3]), "r"(b[0]), "r"(b[1]));
}

__device__ __forceinline__ void split_tf32(float v, uint32_t& hi, uint32_t& lo) {
    uint32_t h;
    asm("cvt.rna.tf32.f32 %0, %1;" : "=r"(h) : "f"(v));
    float l = v - __uint_as_float(h);
    uint32_t lw;
    asm("cvt.rna.tf32.f32 %0, %1;" : "=r"(lw) : "f"(l));
    hi = h; lo = lw;
}

#define TBM 128
#define TBN 128
#define TBK 32
#define ASTRIDE (TBK + 4)
#define BSTRIDE (TBN + 4)

__global__ __launch_bounds__(256) void tf32x3_gemm(
    const float* __restrict__ A, const float* __restrict__ B,
    const float* __restrict__ bias, float* __restrict__ C,
    int M, int N, int K, int hasBias, int relu)
{
    __shared__ float As[TBM * ASTRIDE];   // [m][k]
    __shared__ float Bs[TBK * BSTRIDE];   // [k][n]

    const int tid  = threadIdx.x;
    const int wid  = tid >> 5, lane = tid & 31;
    const int warpM = wid & 1;            // 2 warp-rows of 64
    const int warpN = wid >> 1;           // 4 warp-cols of 32
    const int grp = lane >> 2, tig = lane & 3;

    const int blockRow = blockIdx.y * TBM;
    const int blockCol = blockIdx.x * TBN;

    const int aRow  = tid >> 3;           // 0..31 (+32*rr)
    const int aCol  = (tid & 7) * 4;
    const int bRow8 = tid >> 5;           // 0..7 (+8*rr)
    const int bCol4 = (tid & 31) * 4;

    float acc[4][4][4];
    #pragma unroll
    for (int i = 0; i < 4; i++)
        #pragma unroll
        for (int j = 0; j < 4; j++)
            #pragma unroll
            for (int r = 0; r < 4; r++) acc[i][j][r] = 0.f;

    for (int bk = 0; bk < K; bk += TBK) {
        #pragma unroll
        for (int rr = 0; rr < 4; rr++) {
            int r = aRow + 32 * rr;
            float4 a4 = *reinterpret_cast<const float4*>(
                A + (long)(blockRow + r) * K + bk + aCol);
            *reinterpret_cast<float4*>(&As[r * ASTRIDE + aCol]) = a4;
            int rb = bRow8 + 8 * rr;
            float4 b4 = *reinterpret_cast<const float4*>(
                B + (long)(bk + rb) * N + blockCol + bCol4);
            *reinterpret_cast<float4*>(&Bs[rb * BSTRIDE + bCol4]) = b4;
        }
        __syncthreads();

        #pragma unroll
        for (int kk = 0; kk < TBK; kk += 8) {
            uint32_t ah[4][4], al[4][4];
            #pragma unroll
            for (int mi = 0; mi < 4; mi++) {
                int r0 = warpM * 64 + mi * 16 + grp;
                split_tf32(As[(r0    ) * ASTRIDE + kk + tig    ], ah[mi][0], al[mi][0]);
                split_tf32(As[(r0 + 8) * ASTRIDE + kk + tig    ], ah[mi][1], al[mi][1]);
                split_tf32(As[(r0    ) * ASTRIDE + kk + tig + 4], ah[mi][2], al[mi][2]);
                split_tf32(As[(r0 + 8) * ASTRIDE + kk + tig + 4], ah[mi][3], al[mi][3]);
            }
            uint32_t bh[4][2], bl[4][2];
            #pragma unroll
            for (int ni = 0; ni < 4; ni++) {
                int c0 = warpN * 32 + ni * 8 + grp;
                split_tf32(Bs[(kk + tig    ) * BSTRIDE + c0], bh[ni][0], bl[ni][0]);
                split_tf32(Bs[(kk + tig + 4) * BSTRIDE + c0], bh[ni][1], bl[ni][1]);
            }
            #pragma unroll
            for (int mi = 0; mi < 4; mi++)
                #pragma unroll
                for (int ni = 0; ni < 4; ni++) {
                    mma_tf32(acc[mi][ni], al[mi], bh[ni]);   // lo*hi
                    mma_tf32(acc[mi][ni], ah[mi], bl[ni]);   // hi*lo
                    mma_tf32(acc[mi][ni], ah[mi], bh[ni]);   // hi*hi
                }
        }
        __syncthreads();
    }

    #pragma unroll
    for (int ni = 0; ni < 4; ni++) {
        int col = blockCol + warpN * 32 + ni * 8 + 2 * tig;
        float2 bv = make_float2(0.f, 0.f);
        if (hasBias) bv = *reinterpret_cast<const float2*>(&bias[col]);
        #pragma unroll
        for (int mi = 0; mi < 4; mi++) {
            int row = blockRow + warpM * 64 + mi * 16 + grp;
            float2 o0 = make_float2(acc[mi][ni][0] + bv.x, acc[mi][ni][1] + bv.y);
            float2 o1 = make_float2(acc[mi][ni][2] + bv.x, acc[mi][ni][3] + bv.y);
            if (relu) {
                o0.x = fmaxf(o0.x, 0.f); o0.y = fmaxf(o0.y, 0.f);
                o1.x = fmaxf(o1.x, 0.f); o1.y = fmaxf(o1.y, 0.f);
            }
            *reinterpret_cast<float2*>(&C[(long)row * N + col])       = o0;
            *reinterpret_cast<float2*>(&C[(long)(row + 8) * N + col]) = o1;
        }
    }
}

// ---------------- GCN gather: 4 nodes / block, float4 features ----------------
__global__ __launch_bounds__(256) void gcn_gather4(
    const int* __restrict__ cnt, const int2* __restrict__ csr,
    const float* __restrict__ deg, const float4* __restrict__ hw4,
    const float4* __restrict__ bias4, float4* __restrict__ g4)
{
    int node = blockIdx.x * 4 + (threadIdx.x >> 6);
    int f = threadIdx.x & 63;
    int m = cnt[node]; if (m > CSR_CAP) m = CSR_CAP;
    long base = (long)node * CSR_CAP;

    float inv = 1.0f / deg[node];
    float4 s = hw4[(long)node * 64 + f];
    float4 acc = make_float4(s.x * inv, s.y * inv, s.z * inv, s.w * inv);

    int e = 0;
    for (; e + 4 <= m; e += 4) {
        int2 e0 = csr[base + e + 0], e1 = csr[base + e + 1];
        int2 e2 = csr[base + e + 2], e3 = csr[base + e + 3];
        float c0 = __int_as_float(e0.y), c1 = __int_as_float(e1.y);
        float c2 = __int_as_float(e2.y), c3 = __int_as_float(e3.y);
        float4 v0 = hw4[(long)e0.x * 64 + f];
        float4 v1 = hw4[(long)e1.x * 64 + f];
        float4 v2 = hw4[(long)e2.x * 64 + f];
        float4 v3 = hw4[(long)e3.x * 64 + f];
        acc.x += c0 * v0.x + c1 * v1.x + c2 * v2.x + c3 * v3.x;
        acc.y += c0 * v0.y + c1 * v1.y + c2 * v2.y + c3 * v3.y;
        acc.z += c0 * v0.z + c1 * v1.z + c2 * v2.z + c3 * v3.z;
        acc.w += c0 * v0.w + c1 * v1.w + c2 * v2.w + c3 * v3.w;
    }
    for (; e < m; e++) {
        int2 ee = csr[base + e];
        float cc = __int_as_float(ee.y);
        float4 v = hw4[(long)ee.x * 64 + f];
        acc.x += cc * v.x; acc.y += cc * v.y; acc.z += cc * v.z; acc.w += cc * v.w;
    }
    float4 bb = bias4[f];
    acc.x = fmaxf(acc.x + bb.x, 0.f);
    acc.y = fmaxf(acc.y + bb.y, 0.f);
    acc.z = fmaxf(acc.z + bb.z, 0.f);
    acc.w = fmaxf(acc.w + bb.w, 0.f);
    g4[(long)node * 64 + f] = acc;
}

// ---------------- proto mean + norm (fused) ----------------
__global__ void proto_pn_kernel(const float* __restrict__ t, float* __restrict__ proto,
                                float* __restrict__ pn) {
    int b = blockIdx.x, h = threadIdx.x;
    const float* tb = t + (long)b * NNODES * HD + h;
    float s = 0.f;
    #pragma unroll 4
    for (int n = 0; n < NNODES; n++) s += tb[(long)n * HD];
    float p = s * (1.0f / NNODES);
    proto[b * HD + h] = p;
    __shared__ float red[8];
    float sq = warp_sum(p * p);
    if ((h & 31) == 0) red[h >> 5] = sq;
    __syncthreads();
    if (h == 0) {
        float tot = 0.f;
        #pragma unroll
        for (int i = 0; i < 8; i++) tot += red[i];
        pn[b] = fmaxf(sqrtf(tot), 1e-8f);
    }
}

// ---------------- fused attention + row-normalized mw ----------------
__global__ void att_mw_kernel(const float* __restrict__ t, const float* __restrict__ proto,
                              const float* __restrict__ pn, const float* __restrict__ ew,
                              float* __restrict__ c) {
    int warp = (blockIdx.x * blockDim.x + threadIdx.x) >> 5;
    int lane = threadIdx.x & 31;
    if (warp >= TOTAL_N) return;
    int b = warp >> 9;
    const float* tr = t + (long)warp * HD;
    const float* pr = proto + b * HD;
    float s2 = 0.f, dp = 0.f;
    #pragma unroll
    for (int h = lane; h < HD; h += 32) {
        float tv = tr[h];
        s2 += tv * tv;
        dp += tv * pr[h];
    }
    s2 = warp_sum(s2);
    dp = warp_sum(dp);
    float tn = fmaxf(sqrtf(s2), 1e-8f);
    float a  = 0.5f * (1.0f + dp / (tn * pn[b]));

    const float* er = ew + (long)warp * NV;
    float m0 = er[lane]      * a;
    float m1 = er[lane + 32] * a;
    float rs = warp_sum(m0 + m1);
    float d  = (rs == 0.f) ? 1.f : rs;
    c[(long)warp * NV + lane]      = m0 / d;
    c[(long)warp * NV + lane + 32] = m1 / d;
}

// ---------------- vn[b,v,h] = sum_n c[b,n,v] * g[b,n,h] ----------------
__global__ __launch_bounds__(256) void vn_kernel(const float* __restrict__ c,
                                                 const float* __restrict__ g,
                                                 float* __restrict__ vn) {
    int b = blockIdx.y, v0 = blockIdx.x * 8, h = threadIdx.x;
    __shared__ float sc[NNODES * 8];
    for (int idx = threadIdx.x; idx < NNODES * 8; idx += 256) {
        int n = idx >> 3, vi = idx & 7;
        sc[idx] = c[((long)b * NNODES + n) * NV + v0 + vi];
    }
    __syncthreads();
    const float* gb = g + (long)b * NNODES * HD + h;
    float acc[8] = {0.f};
    for (int n = 0; n < NNODES; n++) {
        float gv = gb[(long)n * HD];
        #pragma unroll
        for (int vi = 0; vi < 8; vi++) acc[vi] += sc[n * 8 + vi] * gv;
    }
    #pragma unroll
    for (int vi = 0; vi < 8; vi++)
        vn[((long)b * NV + v0 + vi) * HD + h] = acc[vi];
}

// ---------------- gf mean + tiny head ----------------
__global__ void gf_kernel(const float* __restrict__ vn2, float* __restrict__ gf) {
    int b = blockIdx.x, h = threadIdx.x;
    float s = 0.f;
    #pragma unroll 4
    for (int v = 0; v < NV; v++) s += vn2[((long)b * NV + v) * HD + h];
    gf[b * HD + h] = s * (1.0f / NV);
}

__global__ void mlp1_kernel(const float* __restrict__ gf, const float* __restrict__ W,
                            const float* __restrict__ bb, float* __restrict__ out) {
    int b = blockIdx.x, h = threadIdx.x;
    __shared__ float sg[HD];
    sg[h] = gf[b * HD + h];
    __syncthreads();
    float acc = 0.f;
    #pragma unroll 4
    for (int k = 0; k < HD; k++) acc += sg[k] * W[k * HD + h];
    out[b * HD + h] = fmaxf(acc + bb[h], 0.f);
}

__global__ void out_kernel(const float* __restrict__ m1, const float* __restrict__ W,
                           const float* __restrict__ bb, float* __restrict__ out) {
    int b = blockIdx.x, tid = threadIdx.x;
    __shared__ float sm[HD];
    sm[tid] = m1[b * HD + tid];
    __syncthreads();
    if (tid < OUT_DIM) {
        float acc = 0.f;
        #pragma unroll 4
        for (int k = 0; k < HD; k++) acc += sm[k] * W[k * OUT_DIM + tid];
        out[b * OUT_DIM + tid] = acc + bb[tid];
    }
}

// ---------------- launch ----------------
extern "C" void kernel_launch(void* const* d_in, const int* in_sizes, int n_in,
                              void* d_out, int out_size) {
    const float* x     = (const float*)d_in[0];
    const int*   esrc  = (const int*)  d_in[1];
    const int*   edst  = (const int*)  d_in[2];
    const float* W_emb = (const float*)d_in[3];
    const float* b_emb = (const float*)d_in[4];
    const float* W_gcn = (const float*)d_in[5];
    const float* b_gcn = (const float*)d_in[6];
    const float* aW1   = (const float*)d_in[7];
    const float* ab1   = (const float*)d_in[8];
    const float* aW2   = (const float*)d_in[9];
    const float* ab2   = (const float*)d_in[10];
    const float* vW1   = (const float*)d_in[11];
    const float* vb1   = (const float*)d_in[12];
    const float* vW2   = (const float*)d_in[13];
    const float* vb2   = (const float*)d_in[14];
    const float* mW1   = (const float*)d_in[15];
    const float* mb1   = (const float*)d_in[16];
    const float* mW2   = (const float*)d_in[17];
    const float* mb2   = (const float*)d_in[18];
    const float* ew    = (const float*)d_in[19];
    float* out = (float*)d_out;

    float *d_deg, *d_wc, *d_bc, *d_hw, *d_g, *d_t1, *d_t, *d_proto, *d_pn,
          *d_c, *d_vn, *d_vnr, *d_vn2, *d_gf, *d_m1;
    int *d_cnt; int2 *d_csr;
    cudaGetSymbolAddress((void**)&d_deg,   g_deg);
    cudaGetSymbolAddress((void**)&d_cnt,   g_cnt);
    cudaGetSymbolAddress((void**)&d_csr,   g_csr);
    cudaGetSymbolAddress((void**)&d_wc,    g_wc);
    cudaGetSymbolAddress((void**)&d_bc,    g_bc);
    cudaGetSymbolAddress((void**)&d_hw,    g_hw);
    cudaGetSymbolAddress((void**)&d_g,     g_g);
    cudaGetSymbolAddress((void**)&d_t1,    g_t1);
    cudaGetSymbolAddress((void**)&d_t,     g_t);
    cudaGetSymbolAddress((void**)&d_proto, g_proto);
    cudaGetSymbolAddress((void**)&d_pn,    g_pn);
    cudaGetSymbolAddress((void**)&d_c,     g_c);
    cudaGetSymbolAddress((void**)&d_vn,    g_vn);
    cudaGetSymbolAddress((void**)&d_vnr,   g_vnr);
    cudaGetSymbolAddress((void**)&d_vn2,   g_vn2);
    cudaGetSymbolAddress((void**)&d_gf,    g_gf);
    cudaGetSymbolAddress((void**)&d_m1,    g_m1);

    // CSR build
    deg_init_kernel<<<TOTAL_N / 256, 256>>>(d_deg, d_cnt);
    deg_count_kernel<<<EDGES / 256, 256>>>(edst, d_deg);
    csr_fill_kernel<<<EDGES / 256, 256>>>(esrc, edst, d_deg, d_cnt, d_csr);

    // fold: Wc = W_emb @ W_gcn (fp32), bc = b_emb @ W_gcn
    sgemm_k<<<dim3(HD / 128, IN_DIM / 128), 256>>>(W_emb, W_gcn, d_wc, IN_DIM, HD, HD);
    bias_combine_kernel<<<1, HD>>>(b_emb, W_gcn, d_bc);

    // hw = x @ Wc + bc
    tf32x3_gemm<<<dim3(HD / TBN, TOTAL_N / TBM), 256>>>(
        x, d_wc, d_bc, d_hw, TOTAL_N, HD, IN_DIM, 1, 0);

    // g = relu(gather(A, hw) + b_gcn)
    gcn_gather4<<<TOTAL_N / 4, 256>>>(d_cnt, d_csr, d_deg,
                                      (const float4*)d_hw, (const float4*)b_gcn,
                                      (float4*)d_g);

    // affinity MLP
    tf32x3_gemm<<<dim3(HD / TBN, TOTAL_N / TBM), 256>>>(
        d_g, aW1, ab1, d_t1, TOTAL_N, HD, HD, 1, 1);
    tf32x3_gemm<<<dim3(HD / TBN, TOTAL_N / TBM), 256>>>(
        d_t1, aW2, ab2, d_t, TOTAL_N, HD, HD, 1, 0);

    proto_pn_kernel<<<NB, HD>>>(d_t, d_proto, d_pn);
    att_mw_kernel<<<TOTAL_N / 8, 256>>>(d_t, d_proto, d_pn, ew, d_c);

    vn_kernel<<<dim3(NV / 8, NB), 256>>>(d_c, d_g, d_vn);

    // virtual-node MLP
    tf32x3_gemm<<<dim3(HD / TBN, (NB * NV) / TBM), 256>>>(
        d_vn, vW1, vb1, d_vnr, NB * NV, HD, HD, 1, 1);
    tf32x3_gemm<<<dim3(HD / TBN, (NB * NV) / TBM), 256>>>(
        d_vnr, vW2, vb2, d_vn2, NB * NV, HD, HD, 1, 0);

    gf_kernel<<<NB, HD>>>(d_vn2, d_gf);
    mlp1_kernel<<<NB, HD>>>(d_gf, mW1, mb1, d_m1);
    out_kernel<<<NB, HD>>>(d_m1, mW2, mb2, out);
}

// round 8
// speedup vs baseline: 1.6007x; 1.0771x over previous
#include <cuda_runtime.h>
#include <cuda_bf16.h>
#include <cstdint>

// ---------------- Problem constants ----------------
#define NB      64
#define NNODES  512
#define NV      64
#define HD      256
#define IN_DIM  128
#define OUT_DIM 10
#define TOTAL_N (NB * NNODES)        // 32768
#define EDGES   (NB * 16384)         // 1048576
#define CSR_CAP 128

// ---------------- Scratch ----------------
__device__ float g_deg[TOTAL_N];
__device__ int   g_cnt[TOTAL_N];
__device__ int2  g_csr[(long)TOTAL_N * CSR_CAP];
__device__ float g_wc[IN_DIM * HD];
__device__ float g_bc[HD];
__device__ float g_y[(long)TOTAL_N * IN_DIM];           // gathered x-space features
__device__ float g_sc[TOTAL_N];                         // per-node coef sum (+1/deg)
__device__ float g_g[(long)TOTAL_N * HD];
__device__ float g_t1[(long)TOTAL_N * HD];
__device__ float g_t[(long)TOTAL_N * HD];
__device__ float g_proto[NB * HD];
__device__ float g_pn[NB];
__device__ float g_c[(long)TOTAL_N * NV];
__device__ float g_vn[(long)NB * NV * HD];
__device__ float g_vnr[(long)NB * NV * HD];
__device__ float g_vn2[(long)NB * NV * HD];
__device__ float g_gf[NB * HD];
__device__ float g_m1[NB * HD];

// ---------------- helpers ----------------
__device__ __forceinline__ float warp_sum(float v) {
    #pragma unroll
    for (int o = 16; o > 0; o >>= 1) v += __shfl_xor_sync(0xffffffff, v, o);
    return v;
}

__global__ void deg_init_kernel(float* __restrict__ deg, int* __restrict__ cnt) {
    int i = blockIdx.x * blockDim.x + threadIdx.x;
    if (i < TOTAL_N) { deg[i] = 1.0f; cnt[i] = 0; }
}

__global__ void deg_count_kernel(const int* __restrict__ dst, float* __restrict__ deg) {
    int e = blockIdx.x * blockDim.x + threadIdx.x;
    if (e < EDGES) atomicAdd(&deg[dst[e]], 1.0f);
}

__global__ void csr_fill_kernel(const int* __restrict__ src, const int* __restrict__ dst,
                                const float* __restrict__ deg,
                                int* __restrict__ cnt, int2* __restrict__ csr) {
    int e = blockIdx.x * blockDim.x + threadIdx.x;
    if (e >= EDGES) return;
    int s = src[e], d = dst[e];
    int pos = atomicAdd(&cnt[d], 1);
    if (pos < CSR_CAP) {
        float coef = rsqrtf(deg[s]) * rsqrtf(deg[d]);
        csr[(long)d * CSR_CAP + pos] = make_int2(s, __float_as_int(coef));
    }
}

// ---------------- weight fold: Wc = W_emb @ W_gcn, bc = b_emb @ W_gcn ----------------
// grid 33: blocks 0..31 compute 4 rows of Wc each; block 32 computes bc.
__global__ __launch_bounds__(256) void fold_kernel(
    const float* __restrict__ W_emb, const float* __restrict__ b_emb,
    const float* __restrict__ W_gcn, float* __restrict__ wc, float* __restrict__ bc)
{
    int c = threadIdx.x;   // output column
    if (blockIdx.x < 32) {
        int r0 = blockIdx.x * 4;
        __shared__ float s[4][HD];
        #pragma unroll
        for (int i = threadIdx.x; i < 4 * HD; i += 256)
            s[i >> 8][i & 255] = W_emb[(r0 + (i >> 8)) * HD + (i & 255)];
        __syncthreads();
        float a0 = 0.f, a1 = 0.f, a2 = 0.f, a3 = 0.f;
        #pragma unroll 4
        for (int k = 0; k < HD; k++) {
            float wg = W_gcn[k * HD + c];
            a0 += s[0][k] * wg; a1 += s[1][k] * wg;
            a2 += s[2][k] * wg; a3 += s[3][k] * wg;
        }
        wc[(r0 + 0) * HD + c] = a0;
        wc[(r0 + 1) * HD + c] = a1;
        wc[(r0 + 2) * HD + c] = a2;
        wc[(r0 + 3) * HD + c] = a3;
    } else {
        __shared__ float sb[HD];
        sb[c] = b_emb[c];
        __syncthreads();
        float a = 0.f;
        #pragma unroll 4
        for (int k = 0; k < HD; k++) a += sb[k] * W_gcn[k * HD + c];
        bc[c] = a;
    }
}

// ---------------- gather in x-space: y[d] = sum coef*x[src] + x[d]/deg; sc = sum coef + 1/deg
// one warp per node, 8 nodes per block; x rows = 32 float4 (coalesced 512B)
__global__ __launch_bounds__(256) void gcn_gather_x(
    const int* __restrict__ cnt, const int2* __restrict__ csr,
    const float* __restrict__ deg, const float4* __restrict__ x4,
    float4* __restrict__ y4, float* __restrict__ sc)
{
    int node = blockIdx.x * 8 + (threadIdx.x >> 5);
    int lane = threadIdx.x & 31;
    int m = cnt[node]; if (m > CSR_CAP) m = CSR_CAP;
    long base = (long)node * CSR_CAP;

    float inv = 1.0f / deg[node];
    float4 a = x4[(long)node * 32 + lane];
    float4 acc = make_float4(a.x * inv, a.y * inv, a.z * inv, a.w * inv);
    float cs = inv;

    int e = 0;
    for (; e + 4 <= m; e += 4) {
        int2 e0 = csr[base + e + 0], e1 = csr[base + e + 1];
        int2 e2 = csr[base + e + 2], e3 = csr[base + e + 3];
        float c0 = __int_as_float(e0.y), c1 = __int_as_float(e1.y);
        float c2 = __int_as_float(e2.y), c3 = __int_as_float(e3.y);
        float4 v0 = x4[(long)e0.x * 32 + lane];
        float4 v1 = x4[(long)e1.x * 32 + lane];
        float4 v2 = x4[(long)e2.x * 32 + lane];
        float4 v3 = x4[(long)e3.x * 32 + lane];
        acc.x += c0 * v0.x + c1 * v1.x + c2 * v2.x + c3 * v3.x;
        acc.y += c0 * v0.y + c1 * v1.y + c2 * v2.y + c3 * v3.y;
        acc.z += c0 * v0.z + c1 * v1.z + c2 * v2.z + c3 * v3.z;
        acc.w += c0 * v0.w + c1 * v1.w + c2 * v2.w + c3 * v3.w;
        cs += c0 + c1 + c2 + c3;
    }
    for (; e < m; e++) {
        int2 ee = csr[base + e];
        float cc = __int_as_float(ee.y);
        float4 v = x4[(long)ee.x * 32 + lane];
        acc.x += cc * v.x; acc.y += cc * v.y; acc.z += cc * v.z; acc.w += cc * v.w;
        cs += cc;
    }
    y4[(long)node * 32 + lane] = acc;
    if (lane == 0) sc[node] = cs;
}

// ---------------- 3xTF32 tensor-core GEMM (fp32-accurate) ----------------
// C = A @ B (+ bias[col]) (+ rowScale[row]*bias2[col]) (relu?)
__device__ __forceinline__ void mma_tf32(float* d, const uint32_t* a, const uint32_t* b) {
    asm volatile(
        "mma.sync.aligned.m16n8k8.row.col.f32.tf32.tf32.f32 "
        "{%0,%1,%2,%3}, {%4,%5,%6,%7}, {%8,%9}, {%0,%1,%2,%3};\n"
        : "+f"(d[0]), "+f"(d[1]), "+f"(d[2]), "+f"(d[3])
        : "r"(a[0]), "r"(a[1]), "r"(a[2]), "r"(a[3]), "r"(b[0]), "r"(b[1]));
}

__device__ __forceinline__ void split_tf32(float v, uint32_t& hi, uint32_t& lo) {
    uint32_t h;
    asm("cvt.rna.tf32.f32 %0, %1;" : "=r"(h) : "f"(v));
    float l = v - __uint_as_float(h);
    uint32_t lw;
    asm("cvt.rna.tf32.f32 %0, %1;" : "=r"(lw) : "f"(l));
    hi = h; lo = lw;
}

#define TBM 128
#define TBN 128
#define TBK 32
#define ASTRIDE (TBK + 4)
#define BSTRIDE (TBN + 4)

__global__ __launch_bounds__(256) void tf32x3_gemm(
    const float* __restrict__ A, const float* __restrict__ B,
    const float* __restrict__ bias, float* __restrict__ C,
    int M, int N, int K, int hasBias, int relu,
    const float* __restrict__ rowScale, const float* __restrict__ bias2, int hasRS)
{
    __shared__ float As[TBM * ASTRIDE];   // [m][k]
    __shared__ float Bs[TBK * BSTRIDE];   // [k][n]

    const int tid  = threadIdx.x;
    const int wid  = tid >> 5, lane = tid & 31;
    const int warpM = wid & 1;
    const int warpN = wid >> 1;
    const int grp = lane >> 2, tig = lane & 3;

    const int blockRow = blockIdx.y * TBM;
    const int blockCol = blockIdx.x * TBN;

    const int aRow  = tid >> 3;
    const int aCol  = (tid & 7) * 4;
    const int bRow8 = tid >> 5;
    const int bCol4 = (tid & 31) * 4;

    float acc[4][4][4];
    #pragma unroll
    for (int i = 0; i < 4; i++)
        #pragma unroll
        for (int j = 0; j < 4; j++)
            #pragma unroll
            for (int r = 0; r < 4; r++) acc[i][j][r] = 0.f;

    for (int bk = 0; bk < K; bk += TBK) {
        #pragma unroll
        for (int rr = 0; rr < 4; rr++) {
            int r = aRow + 32 * rr;
            float4 a4 = *reinterpret_cast<const float4*>(
                A + (long)(blockRow + r) * K + bk + aCol);
            *reinterpret_cast<float4*>(&As[r * ASTRIDE + aCol]) = a4;
            int rb = bRow8 + 8 * rr;
            float4 b4 = *reinterpret_cast<const float4*>(
                B + (long)(bk + rb) * N + blockCol + bCol4);
            *reinterpret_cast<float4*>(&Bs[rb * BSTRIDE + bCol4]) = b4;
        }
        __syncthreads();

        #pragma unroll
        for (int kk = 0; kk < TBK; kk += 8) {
            uint32_t ah[4][4], al[4][4];
            #pragma unroll
            for (int mi = 0; mi < 4; mi++) {
                int r0 = warpM * 64 + mi * 16 + grp;
                split_tf32(As[(r0    ) * ASTRIDE + kk + tig    ], ah[mi][0], al[mi][0]);
                split_tf32(As[(r0 + 8) * ASTRIDE + kk + tig    ], ah[mi][1], al[mi][1]);
                split_tf32(As[(r0    ) * ASTRIDE + kk + tig + 4], ah[mi][2], al[mi][2]);
                split_tf32(As[(r0 + 8) * ASTRIDE + kk + tig + 4], ah[mi][3], al[mi][3]);
            }
            uint32_t bh[4][2], bl[4][2];
            #pragma unroll
            for (int ni = 0; ni < 4; ni++) {
                int c0 = warpN * 32 + ni * 8 + grp;
                split_tf32(Bs[(kk + tig    ) * BSTRIDE + c0], bh[ni][0], bl[ni][0]);
                split_tf32(Bs[(kk + tig + 4) * BSTRIDE + c0], bh[ni][1], bl[ni][1]);
            }
            #pragma unroll
            for (int mi = 0; mi < 4; mi++)
                #pragma unroll
                for (int ni = 0; ni < 4; ni++) {
                    mma_tf32(acc[mi][ni], al[mi], bh[ni]);
                    mma_tf32(acc[mi][ni], ah[mi], bl[ni]);
                    mma_tf32(acc[mi][ni], ah[mi], bh[ni]);
                }
        }
        __syncthreads();
    }

    #pragma unroll
    for (int mi = 0; mi < 4; mi++) {
        int row = blockRow + warpM * 64 + mi * 16 + grp;
        float rs0 = 0.f, rs1 = 0.f;
        if (hasRS) { rs0 = rowScale[row]; rs1 = rowScale[row + 8]; }
        #pragma unroll
        for (int ni = 0; ni < 4; ni++) {
            int col = blockCol + warpN * 32 + ni * 8 + 2 * tig;
            float2 bv = make_float2(0.f, 0.f);
            if (hasBias) bv = *reinterpret_cast<const float2*>(&bias[col]);
            float2 b2 = make_float2(0.f, 0.f);
            if (hasRS) b2 = *reinterpret_cast<const float2*>(&bias2[col]);
            float2 o0 = make_float2(acc[mi][ni][0] + bv.x + rs0 * b2.x,
                                    acc[mi][ni][1] + bv.y + rs0 * b2.y);
            float2 o1 = make_float2(acc[mi][ni][2] + bv.x + rs1 * b2.x,
                                    acc[mi][ni][3] + bv.y + rs1 * b2.y);
            if (relu) {
                o0.x = fmaxf(o0.x, 0.f); o0.y = fmaxf(o0.y, 0.f);
                o1.x = fmaxf(o1.x, 0.f); o1.y = fmaxf(o1.y, 0.f);
            }
            *reinterpret_cast<float2*>(&C[(long)row * N + col])       = o0;
            *reinterpret_cast<float2*>(&C[(long)(row + 8) * N + col]) = o1;
        }
    }
}

// ---------------- proto mean + norm (fused) ----------------
__global__ void proto_pn_kernel(const float* __restrict__ t, float* __restrict__ proto,
                                float* __restrict__ pn) {
    int b = blockIdx.x, h = threadIdx.x;
    const float* tb = t + (long)b * NNODES * HD + h;
    float s = 0.f;
    #pragma unroll 4
    for (int n = 0; n < NNODES; n++) s += tb[(long)n * HD];
    float p = s * (1.0f / NNODES);
    proto[b * HD + h] = p;
    __shared__ float red[8];
    float sq = warp_sum(p * p);
    if ((h & 31) == 0) red[h >> 5] = sq;
    __syncthreads();
    if (h == 0) {
        float tot = 0.f;
        #pragma unroll
        for (int i = 0; i < 8; i++) tot += red[i];
        pn[b] = fmaxf(sqrtf(tot), 1e-8f);
    }
}

// ---------------- fused attention + row-normalized mw ----------------
__global__ void att_mw_kernel(const float* __restrict__ t, const float* __restrict__ proto,
                              const float* __restrict__ pn, const float* __restrict__ ew,
                              float* __restrict__ c) {
    int warp = (blockIdx.x * blockDim.x + threadIdx.x) >> 5;
    int lane = threadIdx.x & 31;
    if (warp >= TOTAL_N) return;
    int b = warp >> 9;
    const float* tr = t + (long)warp * HD;
    const float* pr = proto + b * HD;
    float s2 = 0.f, dp = 0.f;
    #pragma unroll
    for (int h = lane; h < HD; h += 32) {
        float tv = tr[h];
        s2 += tv * tv;
        dp += tv * pr[h];
    }
    s2 = warp_sum(s2);
    dp = warp_sum(dp);
    float tn = fmaxf(sqrtf(s2), 1e-8f);
    float a  = 0.5f * (1.0f + dp / (tn * pn[b]));

    const float* er = ew + (long)warp * NV;
    float m0 = er[lane]      * a;
    float m1 = er[lane + 32] * a;
    float rs = warp_sum(m0 + m1);
    float d  = (rs == 0.f) ? 1.f : rs;
    c[(long)warp * NV + lane]      = m0 / d;
    c[(long)warp * NV + lane + 32] = m1 / d;
}

// ---------------- vn[b,v,h] = sum_n c[b,n,v] * g[b,n,h] ----------------
__global__ __launch_bounds__(256) void vn_kernel(const float* __restrict__ c,
                                                 const float* __restrict__ g,
                                                 float* __restrict__ vn) {
    int b = blockIdx.y, v0 = blockIdx.x * 8, h = threadIdx.x;
    __shared__ float sc[NNODES * 8];
    for (int idx = threadIdx.x; idx < NNODES * 8; idx += 256) {
        int n = idx >> 3, vi = idx & 7;
        sc[idx] = c[((long)b * NNODES + n) * NV + v0 + vi];
    }
    __syncthreads();
    const float* gb = g + (long)b * NNODES * HD + h;
    float acc[8] = {0.f};
    for (int n = 0; n < NNODES; n++) {
        float gv = gb[(long)n * HD];
        #pragma unroll
        for (int vi = 0; vi < 8; vi++) acc[vi] += sc[n * 8 + vi] * gv;
    }
    #pragma unroll
    for (int vi = 0; vi < 8; vi++)
        vn[((long)b * NV + v0 + vi) * HD + h] = acc[vi];
}

// ---------------- gf mean + tiny head ----------------
__global__ void gf_kernel(const float* __restrict__ vn2, float* __restrict__ gf) {
    int b = blockIdx.x, h = threadIdx.x;
    float s = 0.f;
    #pragma unroll 4
    for (int v = 0; v < NV; v++) s += vn2[((long)b * NV + v) * HD + h];
    gf[b * HD + h] = s * (1.0f / NV);
}

__global__ void mlp1_kernel(const float* __restrict__ gf, const float* __restrict__ W,
                            const float* __restrict__ bb, float* __restrict__ out) {
    int b = blockIdx.x, h = threadIdx.x;
    __shared__ float sg[HD];
    sg[h] = gf[b * HD + h];
    __syncthreads();
    float acc = 0.f;
    #pragma unroll 4
    for (int k = 0; k < HD; k++) acc += sg[k] * W[k * HD + h];
    out[b * HD + h] = fmaxf(acc + bb[h], 0.f);
}

__global__ void out_kernel(const float* __restrict__ m1, const float* __restrict__ W,
                           const float* __restrict__ bb, float* __restrict__ out) {
    int b = blockIdx.x, tid = threadIdx.x;
    __shared__ float sm[HD];
    sm[tid] = m1[b * HD + tid];
    __syncthreads();
    if (tid < OUT_DIM) {
        float acc = 0.f;
        #pragma unroll 4
        for (int k = 0; k < HD; k++) acc += sm[k] * W[k * OUT_DIM + tid];
        out[b * OUT_DIM + tid] = acc + bb[tid];
    }
}

// ---------------- launch ----------------
extern "C" void kernel_launch(void* const* d_in, const int* in_sizes, int n_in,
                              void* d_out, int out_size) {
    const float* x     = (const float*)d_in[0];
    const int*   esrc  = (const int*)  d_in[1];
    const int*   edst  = (const int*)  d_in[2];
    const float* W_emb = (const float*)d_in[3];
    const float* b_emb = (const float*)d_in[4];
    const float* W_gcn = (const float*)d_in[5];
    const float* b_gcn = (const float*)d_in[6];
    const float* aW1   = (const float*)d_in[7];
    const float* ab1   = (const float*)d_in[8];
    const float* aW2   = (const float*)d_in[9];
    const float* ab2   = (const float*)d_in[10];
    const float* vW1   = (const float*)d_in[11];
    const float* vb1   = (const float*)d_in[12];
    const float* vW2   = (const float*)d_in[13];
    const float* vb2   = (const float*)d_in[14];
    const float* mW1   = (const float*)d_in[15];
    const float* mb1   = (const float*)d_in[16];
    const float* mW2   = (const float*)d_in[17];
    const float* mb2   = (const float*)d_in[18];
    const float* ew    = (const float*)d_in[19];
    float* out = (float*)d_out;

    float *d_deg, *d_wc, *d_bc, *d_y, *d_sc, *d_g, *d_t1, *d_t, *d_proto, *d_pn,
          *d_c, *d_vn, *d_vnr, *d_vn2, *d_gf, *d_m1;
    int *d_cnt; int2 *d_csr;
    cudaGetSymbolAddress((void**)&d_deg,   g_deg);
    cudaGetSymbolAddress((void**)&d_cnt,   g_cnt);
    cudaGetSymbolAddress((void**)&d_csr,   g_csr);
    cudaGetSymbolAddress((void**)&d_wc,    g_wc);
    cudaGetSymbolAddress((void**)&d_bc,    g_bc);
    cudaGetSymbolAddress((void**)&d_y,     g_y);
    cudaGetSymbolAddress((void**)&d_sc,    g_sc);
    cudaGetSymbolAddress((void**)&d_g,     g_g);
    cudaGetSymbolAddress((void**)&d_t1,    g_t1);
    cudaGetSymbolAddress((void**)&d_t,     g_t);
    cudaGetSymbolAddress((void**)&d_proto, g_proto);
    cudaGetSymbolAddress((void**)&d_pn,    g_pn);
    cudaGetSymbolAddress((void**)&d_c,     g_c);
    cudaGetSymbolAddress((void**)&d_vn,    g_vn);
    cudaGetSymbolAddress((void**)&d_vnr,   g_vnr);
    cudaGetSymbolAddress((void**)&d_vn2,   g_vn2);
    cudaGetSymbolAddress((void**)&d_gf,    g_gf);
    cudaGetSymbolAddress((void**)&d_m1,    g_m1);

    // CSR build
    deg_init_kernel<<<TOTAL_N / 256, 256>>>(d_deg, d_cnt);
    deg_count_kernel<<<EDGES / 256, 256>>>(edst, d_deg);
    csr_fill_kernel<<<EDGES / 256, 256>>>(esrc, edst, d_deg, d_cnt, d_csr);

    // weight fold (parallel): Wc = W_emb@W_gcn, bc = b_emb@W_gcn
    fold_kernel<<<33, 256>>>(W_emb, b_emb, W_gcn, d_wc, d_bc);

    // sparse aggregation in x-space (half the feature width)
    gcn_gather_x<<<TOTAL_N / 8, 256>>>(d_cnt, d_csr, d_deg,
                                       (const float4*)x, (float4*)d_y, d_sc);

    // g = relu(y @ Wc + sc*bc + b_gcn)
    tf32x3_gemm<<<dim3(HD / TBN, TOTAL_N / TBM), 256>>>(
        d_y, d_wc, b_gcn, d_g, TOTAL_N, HD, IN_DIM, 1, 1, d_sc, d_bc, 1);

    // affinity MLP
    tf32x3_gemm<<<dim3(HD / TBN, TOTAL_N / TBM), 256>>>(
        d_g, aW1, ab1, d_t1, TOTAL_N, HD, HD, 1, 1, nullptr, nullptr, 0);
    tf32x3_gemm<<<dim3(HD / TBN, TOTAL_N / TBM), 256>>>(
        d_t1, aW2, ab2, d_t, TOTAL_N, HD, HD, 1, 0, nullptr, nullptr, 0);

    proto_pn_kernel<<<NB, HD>>>(d_t, d_proto, d_pn);
    att_mw_kernel<<<TOTAL_N / 8, 256>>>(d_t, d_proto, d_pn, ew, d_c);

    vn_kernel<<<dim3(NV / 8, NB), 256>>>(d_c, d_g, d_vn);

    // virtual-node MLP
    tf32x3_gemm<<<dim3(HD / TBN, (NB * NV) / TBM), 256>>>(
        d_vn, vW1, vb1, d_vnr, NB * NV, HD, HD, 1, 1, nullptr, nullptr, 0);
    tf32x3_gemm<<<dim3(HD / TBN, (NB * NV) / TBM), 256>>>(
        d_vnr, vW2, vb2, d_vn2, NB * NV, HD, HD, 1, 0, nullptr, nullptr, 0);

    gf_kernel<<<NB, HD>>>(d_vn2, d_gf);
    mlp1_kernel<<<NB, HD>>>(d_gf, mW1, mb1, d_m1);
    out_kernel<<<NB, HD>>>(d_m1, mW2, mb2, out);
}

// round 9
// speedup vs baseline: 1.7552x; 1.0965x over previous
#include <cuda_runtime.h>
#include <cuda_bf16.h>
#include <cstdint>

// ---------------- Problem constants ----------------
#define NB      64
#define NNODES  512
#define NV      64
#define HD      256
#define IN_DIM  128
#define OUT_DIM 10
#define TOTAL_N (NB * NNODES)        // 32768
#define EDGES   (NB * 16384)         // 1048576
#define CSR_CAP 128

// ---------------- Scratch ----------------
__device__ int   g_cnt[TOTAL_N];
__device__ float g_dinv[TOTAL_N];
__device__ int   g_csr[(long)TOTAL_N * CSR_CAP];        // src only (4B/edge slot)
__device__ float g_wc[IN_DIM * HD];
__device__ float g_bc[HD];
__device__ float g_y[(long)TOTAL_N * IN_DIM];           // gathered x-space features
__device__ float g_sc[TOTAL_N];                         // per-node coef sum (+1/deg)
__device__ float g_g[(long)TOTAL_N * HD];
__device__ float g_t1[(long)TOTAL_N * HD];
__device__ float g_t[(long)TOTAL_N * HD];
__device__ float g_proto[NB * HD];
__device__ float g_pn[NB];
__device__ float g_ct[(long)NB * NV * NNODES];          // c transposed [b][v][n]
__device__ float g_vn[(long)NB * NV * HD];
__device__ float g_vnr[(long)NB * NV * HD];
__device__ float g_vn2[(long)NB * NV * HD];
__device__ float g_gf[NB * HD];
__device__ float g_m1[NB * HD];

// ---------------- helpers ----------------
__device__ __forceinline__ float warp_sum(float v) {
    #pragma unroll
    for (int o = 16; o > 0; o >>= 1) v += __shfl_xor_sync(0xffffffff, v, o);
    return v;
}

__global__ void cnt_zero_kernel(int* __restrict__ cnt) {
    int i = blockIdx.x * blockDim.x + threadIdx.x;
    if (i < TOTAL_N) cnt[i] = 0;
}

__global__ void csr_fill_kernel(const int* __restrict__ src, const int* __restrict__ dst,
                                int* __restrict__ cnt, int* __restrict__ csr) {
    int e = blockIdx.x * blockDim.x + threadIdx.x;
    if (e >= EDGES) return;
    int s = src[e], d = dst[e];
    int pos = atomicAdd(&cnt[d], 1);
    if (pos < CSR_CAP) csr[(long)d * CSR_CAP + pos] = s;
}

__global__ void dinv_kernel(const int* __restrict__ cnt, float* __restrict__ dinv) {
    int i = blockIdx.x * blockDim.x + threadIdx.x;
    if (i < TOTAL_N) dinv[i] = rsqrtf(1.0f + (float)cnt[i]);
}

// ---------------- tiled weight fold: Wc = W_emb@W_gcn, bc = b_emb@W_gcn ----------------
// 16 blocks x 8 rows; block 0 additionally computes bc as a 9th accumulator.
__global__ __launch_bounds__(256) void fold2_kernel(
    const float* __restrict__ W_emb, const float* __restrict__ b_emb,
    const float* __restrict__ W_gcn, float* __restrict__ wc, float* __restrict__ bc)
{
    __shared__ float we_s[9][HD];    // 8 W_emb rows (+ b_emb in block 0)
    __shared__ float wgs[32][HD];    // 32-row chunk of W_gcn
    const int tid = threadIdx.x;
    const int c = tid;               // output column
    const int r0 = blockIdx.x * 8;

    // stage 8 contiguous W_emb rows (2048 floats = 512 float4)
    const float4* we4 = reinterpret_cast<const float4*>(W_emb + (long)r0 * HD);
    #pragma unroll
    for (int i = tid; i < 512; i += 256)
        reinterpret_cast<float4*>(we_s)[i] = we4[i];
    // row 8: b_emb (block 0) or zeros (others)
    if (tid < 64) {
        float4 v = (blockIdx.x == 0)
                 ? reinterpret_cast<const float4*>(b_emb)[tid]
                 : make_float4(0.f, 0.f, 0.f, 0.f);
        reinterpret_cast<float4*>(&we_s[8][0])[tid] = v;
    }

    float acc[9];
    #pragma unroll
    for (int r = 0; r < 9; r++) acc[r] = 0.f;

    for (int kc = 0; kc < HD; kc += 32) {
        __syncthreads();
        const float4* wg4 = reinterpret_cast<const float4*>(W_gcn + (long)kc * HD);
        #pragma unroll
        for (int i = tid; i < 2048; i += 256)
            reinterpret_cast<float4*>(wgs)[i] = wg4[i];
        __syncthreads();
        #pragma unroll
        for (int k = 0; k < 32; k++) {
            float w = wgs[k][c];
            #pragma unroll
            for (int r = 0; r < 9; r++) acc[r] += we_s[r][kc + k] * w;
        }
    }
    #pragma unroll
    for (int r = 0; r < 8; r++) wc[(long)(r0 + r) * HD + c] = acc[r];
    if (blockIdx.x == 0) bc[c] = acc[8];
}

// ---------------- gather in x-space (coef computed on the fly from dinv) ----------------
__global__ __launch_bounds__(256) void gcn_gather_x(
    const int* __restrict__ cnt, const int* __restrict__ csr,
    const float* __restrict__ dinv, const float4* __restrict__ x4,
    float4* __restrict__ y4, float* __restrict__ sc)
{
    int node = blockIdx.x * 8 + (threadIdx.x >> 5);
    int lane = threadIdx.x & 31;
    int mr = cnt[node];
    int m = mr > CSR_CAP ? CSR_CAP : mr;
    long base = (long)node * CSR_CAP;

    float dd  = 1.0f + (float)mr;
    float inv = 1.0f / dd;
    float rsd = dinv[node];

    float4 a = x4[(long)node * 32 + lane];
    float4 acc = make_float4(a.x * inv, a.y * inv, a.z * inv, a.w * inv);
    float cs = inv;

    int e = 0;
    for (; e + 4 <= m; e += 4) {
        int s0 = csr[base + e + 0], s1 = csr[base + e + 1];
        int s2 = csr[base + e + 2], s3 = csr[base + e + 3];
        float c0 = dinv[s0] * rsd, c1 = dinv[s1] * rsd;
        float c2 = dinv[s2] * rsd, c3 = dinv[s3] * rsd;
        float4 v0 = x4[(long)s0 * 32 + lane];
        float4 v1 = x4[(long)s1 * 32 + lane];
        float4 v2 = x4[(long)s2 * 32 + lane];
        float4 v3 = x4[(long)s3 * 32 + lane];
        acc.x += c0 * v0.x + c1 * v1.x + c2 * v2.x + c3 * v3.x;
        acc.y += c0 * v0.y + c1 * v1.y + c2 * v2.y + c3 * v3.y;
        acc.z += c0 * v0.z + c1 * v1.z + c2 * v2.z + c3 * v3.z;
        acc.w += c0 * v0.w + c1 * v1.w + c2 * v2.w + c3 * v3.w;
        cs += c0 + c1 + c2 + c3;
    }
    for (; e < m; e++) {
        int s0 = csr[base + e];
        float cc = dinv[s0] * rsd;
        float4 v = x4[(long)s0 * 32 + lane];
        acc.x += cc * v.x; acc.y += cc * v.y; acc.z += cc * v.z; acc.w += cc * v.w;
        cs += cc;
    }
    y4[(long)node * 32 + lane] = acc;
    if (lane == 0) sc[node] = cs;
}

// ---------------- 3xTF32 tensor-core GEMM (fp32-accurate) ----------------
__device__ __forceinline__ void mma_tf32(float* d, const uint32_t* a, const uint32_t* b) {
    asm volatile(
        "mma.sync.aligned.m16n8k8.row.col.f32.tf32.tf32.f32 "
        "{%0,%1,%2,%3}, {%4,%5,%6,%7}, {%8,%9}, {%0,%1,%2,%3};\n"
        : "+f"(d[0]), "+f"(d[1]), "+f"(d[2]), "+f"(d[3])
        : "r"(a[0]), "r"(a[1]), "r"(a[2]), "r"(a[3]), "r"(b[0]), "r"(b[1]));
}

__device__ __forceinline__ void split_tf32(float v, uint32_t& hi, uint32_t& lo) {
    uint32_t h;
    asm("cvt.rna.tf32.f32 %0, %1;" : "=r"(h) : "f"(v));
    float l = v - __uint_as_float(h);
    uint32_t lw;
    asm("cvt.rna.tf32.f32 %0, %1;" : "=r"(lw) : "f"(l));
    hi = h; lo = lw;
}

#define TBM 128
#define TBN 128
#define TBK 32
#define ASTRIDE (TBK + 4)
#define BSTRIDE (TBN + 4)

__global__ __launch_bounds__(256) void tf32x3_gemm(
    const float* __restrict__ A, const float* __restrict__ B,
    const float* __restrict__ bias, float* __restrict__ C,
    int M, int N, int K, int hasBias, int relu,
    const float* __restrict__ rowScale, const float* __restrict__ bias2, int hasRS)
{
    __shared__ float As[TBM * ASTRIDE];
    __shared__ float Bs[TBK * BSTRIDE];

    const int tid  = threadIdx.x;
    const int wid  = tid >> 5, lane = tid & 31;
    const int warpM = wid & 1;
    const int warpN = wid >> 1;
    const int grp = lane >> 2, tig = lane & 3;

    const int blockRow = blockIdx.y * TBM;
    const int blockCol = blockIdx.x * TBN;

    const int aRow  = tid >> 3;
    const int aCol  = (tid & 7) * 4;
    const int bRow8 = tid >> 5;
    const int bCol4 = (tid & 31) * 4;

    float acc[4][4][4];
    #pragma unroll
    for (int i = 0; i < 4; i++)
        #pragma unroll
        for (int j = 0; j < 4; j++)
            #pragma unroll
            for (int r = 0; r < 4; r++) acc[i][j][r] = 0.f;

    for (int bk = 0; bk < K; bk += TBK) {
        #pragma unroll
        for (int rr = 0; rr < 4; rr++) {
            int r = aRow + 32 * rr;
            float4 a4 = *reinterpret_cast<const float4*>(
                A + (long)(blockRow + r) * K + bk + aCol);
            *reinterpret_cast<float4*>(&As[r * ASTRIDE + aCol]) = a4;
            int rb = bRow8 + 8 * rr;
            float4 b4 = *reinterpret_cast<const float4*>(
                B + (long)(bk + rb) * N + blockCol + bCol4);
            *reinterpret_cast<float4*>(&Bs[rb * BSTRIDE + bCol4]) = b4;
        }
        __syncthreads();

        #pragma unroll
        for (int kk = 0; kk < TBK; kk += 8) {
            uint32_t ah[4][4], al[4][4];
            #pragma unroll
            for (int mi = 0; mi < 4; mi++) {
                int r0 = warpM * 64 + mi * 16 + grp;
                split_tf32(As[(r0    ) * ASTRIDE + kk + tig    ], ah[mi][0], al[mi][0]);
                split_tf32(As[(r0 + 8) * ASTRIDE + kk + tig    ], ah[mi][1], al[mi][1]);
                split_tf32(As[(r0    ) * ASTRIDE + kk + tig + 4], ah[mi][2], al[mi][2]);
                split_tf32(As[(r0 + 8) * ASTRIDE + kk + tig + 4], ah[mi][3], al[mi][3]);
            }
            uint32_t bh[4][2], bl[4][2];
            #pragma unroll
            for (int ni = 0; ni < 4; ni++) {
                int c0 = warpN * 32 + ni * 8 + grp;
                split_tf32(Bs[(kk + tig    ) * BSTRIDE + c0], bh[ni][0], bl[ni][0]);
                split_tf32(Bs[(kk + tig + 4) * BSTRIDE + c0], bh[ni][1], bl[ni][1]);
            }
            #pragma unroll
            for (int mi = 0; mi < 4; mi++)
                #pragma unroll
                for (int ni = 0; ni < 4; ni++) {
                    mma_tf32(acc[mi][ni], al[mi], bh[ni]);
                    mma_tf32(acc[mi][ni], ah[mi], bl[ni]);
                    mma_tf32(acc[mi][ni], ah[mi], bh[ni]);
                }
        }
        __syncthreads();
    }

    #pragma unroll
    for (int mi = 0; mi < 4; mi++) {
        int row = blockRow + warpM * 64 + mi * 16 + grp;
        float rs0 = 0.f, rs1 = 0.f;
        if (hasRS) { rs0 = rowScale[row]; rs1 = rowScale[row + 8]; }
        #pragma unroll
        for (int ni = 0; ni < 4; ni++) {
            int col = blockCol + warpN * 32 + ni * 8 + 2 * tig;
            float2 bv = make_float2(0.f, 0.f);
            if (hasBias) bv = *reinterpret_cast<const float2*>(&bias[col]);
            float2 b2 = make_float2(0.f, 0.f);
            if (hasRS) b2 = *reinterpret_cast<const float2*>(&bias2[col]);
            float2 o0 = make_float2(acc[mi][ni][0] + bv.x + rs0 * b2.x,
                                    acc[mi][ni][1] + bv.y + rs0 * b2.y);
            float2 o1 = make_float2(acc[mi][ni][2] + bv.x + rs1 * b2.x,
                                    acc[mi][ni][3] + bv.y + rs1 * b2.y);
            if (relu) {
                o0.x = fmaxf(o0.x, 0.f); o0.y = fmaxf(o0.y, 0.f);
                o1.x = fmaxf(o1.x, 0.f); o1.y = fmaxf(o1.y, 0.f);
            }
            *reinterpret_cast<float2*>(&C[(long)row * N + col])       = o0;
            *reinterpret_cast<float2*>(&C[(long)(row + 8) * N + col]) = o1;
        }
    }
}

// ---------------- batched 3xTF32 GEMM for vn: C[z](64x256) = A[z](64x512) @ B[z](512x256) ----
__global__ __launch_bounds__(256) void vn_gemm(
    const float* __restrict__ Am, const float* __restrict__ Bm, float* __restrict__ Cm)
{
    __shared__ float As[NV * ASTRIDE];    // 64 x 36
    __shared__ float Bs[TBK * BSTRIDE];

    const int tid  = threadIdx.x;
    const int wid  = tid >> 5, lane = tid & 31;
    const int warpM = wid & 1;            // 2 x 32 rows
    const int warpN = wid >> 1;           // 4 x 32 cols
    const int grp = lane >> 2, tig = lane & 3;

    const int z = blockIdx.z;
    const float* A = Am + (long)z * NV * NNODES;     // 64 x 512 row-major
    const float* B = Bm + (long)z * NNODES * HD;     // 512 x 256 row-major
    float*       C = Cm + (long)z * NV * HD;
    const int blockCol = blockIdx.x * TBN;

    const int aRow  = tid >> 3;           // 0..31 (+32)
    const int aCol  = (tid & 7) * 4;
    const int bRow8 = tid >> 5;
    const int bCol4 = (tid & 31) * 4;

    float acc[2][4][4];
    #pragma unroll
    for (int i = 0; i < 2; i++)
        #pragma unroll
        for (int j = 0; j < 4; j++)
            #pragma unroll
            for (int r = 0; r < 4; r++) acc[i][j][r] = 0.f;

    for (int bk = 0; bk < NNODES; bk += TBK) {
        #pragma unroll
        for (int rr = 0; rr < 2; rr++) {
            int r = aRow + 32 * rr;
            float4 a4 = *reinterpret_cast<const float4*>(A + (long)r * NNODES + bk + aCol);
            *reinterpret_cast<float4*>(&As[r * ASTRIDE + aCol]) = a4;
        }
        #pragma unroll
        for (int rr = 0; rr < 4; rr++) {
            int rb = bRow8 + 8 * rr;
            float4 b4 = *reinterpret_cast<const float4*>(B + (long)(bk + rb) * HD + blockCol + bCol4);
            *reinterpret_cast<float4*>(&Bs[rb * BSTRIDE + bCol4]) = b4;
        }
        __syncthreads();

        #pragma unroll
        for (int kk = 0; kk < TBK; kk += 8) {
            uint32_t ah[2][4], al[2][4];
            #pragma unroll
            for (int mi = 0; mi < 2; mi++) {
                int r0 = warpM * 32 + mi * 16 + grp;
                split_tf32(As[(r0    ) * ASTRIDE + kk + tig    ], ah[mi][0], al[mi][0]);
                split_tf32(As[(r0 + 8) * ASTRIDE + kk + tig    ], ah[mi][1], al[mi][1]);
                split_tf32(As[(r0    ) * ASTRIDE + kk + tig + 4], ah[mi][2], al[mi][2]);
                split_tf32(As[(r0 + 8) * ASTRIDE + kk + tig + 4], ah[mi][3], al[mi][3]);
            }
            uint32_t bh[4][2], bl[4][2];
            #pragma unroll
            for (int ni = 0; ni < 4; ni++) {
                int c0 = warpN * 32 + ni * 8 + grp;
                split_tf32(Bs[(kk + tig    ) * BSTRIDE + c0], bh[ni][0], bl[ni][0]);
                split_tf32(Bs[(kk + tig + 4) * BSTRIDE + c0], bh[ni][1], bl[ni][1]);
            }
            #pragma unroll
            for (int mi = 0; mi < 2; mi++)
                #pragma unroll
                for (int ni = 0; ni < 4; ni++) {
                    mma_tf32(acc[mi][ni], al[mi], bh[ni]);
                    mma_tf32(acc[mi][ni], ah[mi], bl[ni]);
                    mma_tf32(acc[mi][ni], ah[mi], bh[ni]);
                }
        }
        __syncthreads();
    }

    #pragma unroll
    for (int mi = 0; mi < 2; mi++) {
        int row = warpM * 32 + mi * 16 + grp;
        #pragma unroll
        for (int ni = 0; ni < 4; ni++) {
            int col = blockCol + warpN * 32 + ni * 8 + 2 * tig;
            *reinterpret_cast<float2*>(&C[(long)row * HD + col]) =
                make_float2(acc[mi][ni][0], acc[mi][ni][1]);
            *reinterpret_cast<float2*>(&C[(long)(row + 8) * HD + col]) =
                make_float2(acc[mi][ni][2], acc[mi][ni][3]);
        }
    }
}

// ---------------- proto mean + norm (fused) ----------------
__global__ void proto_pn_kernel(const float* __restrict__ t, float* __restrict__ proto,
                                float* __restrict__ pn) {
    int b = blockIdx.x, h = threadIdx.x;
    const float* tb = t + (long)b * NNODES * HD + h;
    float s = 0.f;
    #pragma unroll 4
    for (int n = 0; n < NNODES; n++) s += tb[(long)n * HD];
    float p = s * (1.0f / NNODES);
    proto[b * HD + h] = p;
    __shared__ float red[8];
    float sq = warp_sum(p * p);
    if ((h & 31) == 0) red[h >> 5] = sq;
    __syncthreads();
    if (h == 0) {
        float tot = 0.f;
        #pragma unroll
        for (int i = 0; i < 8; i++) tot += red[i];
        pn[b] = fmaxf(sqrtf(tot), 1e-8f);
    }
}

// ---------------- fused attention + row-normalized mw (writes TRANSPOSED c) ----------------
__global__ void att_mw_kernel(const float* __restrict__ t, const float* __restrict__ proto,
                              const float* __restrict__ pn, const float* __restrict__ ew,
                              float* __restrict__ ct) {
    int warp = (blockIdx.x * blockDim.x + threadIdx.x) >> 5;
    int lane = threadIdx.x & 31;
    if (warp >= TOTAL_N) return;
    int b  = warp >> 9;
    int nl = warp & 511;
    const float* tr = t + (long)warp * HD;
    const float* pr = proto + b * HD;
    float s2 = 0.f, dp = 0.f;
    #pragma unroll
    for (int h = lane; h < HD; h += 32) {
        float tv = tr[h];
        s2 += tv * tv;
        dp += tv * pr[h];
    }
    s2 = warp_sum(s2);
    dp = warp_sum(dp);
    float tn = fmaxf(sqrtf(s2), 1e-8f);
    float a  = 0.5f * (1.0f + dp / (tn * pn[b]));

    const float* er = ew + (long)warp * NV;
    float m0 = er[lane]      * a;
    float m1 = er[lane + 32] * a;
    float rs = warp_sum(m0 + m1);
    float d  = (rs == 0.f) ? 1.f : rs;
    // transposed: ct[b][v][n]
    ct[((long)b * NV + lane)      * NNODES + nl] = m0 / d;
    ct[((long)b * NV + lane + 32) * NNODES + nl] = m1 / d;
}

// ---------------- gf mean + tiny head ----------------
__global__ void gf_kernel(const float* __restrict__ vn2, float* __restrict__ gf) {
    int b = blockIdx.x, h = threadIdx.x;
    float s = 0.f;
    #pragma unroll 4
    for (int v = 0; v < NV; v++) s += vn2[((long)b * NV + v) * HD + h];
    gf[b * HD + h] = s * (1.0f / NV);
}

__global__ void mlp1_kernel(const float* __restrict__ gf, const float* __restrict__ W,
                            const float* __restrict__ bb, float* __restrict__ out) {
    int b = blockIdx.x, h = threadIdx.x;
    __shared__ float sg[HD];
    sg[h] = gf[b * HD + h];
    __syncthreads();
    float acc = 0.f;
    #pragma unroll 4
    for (int k = 0; k < HD; k++) acc += sg[k] * W[k * HD + h];
    out[b * HD + h] = fmaxf(acc + bb[h], 0.f);
}

__global__ void out_kernel(const float* __restrict__ m1, const float* __restrict__ W,
                           const float* __restrict__ bb, float* __restrict__ out) {
    int b = blockIdx.x, tid = threadIdx.x;
    __shared__ float sm[HD];
    sm[tid] = m1[b * HD + tid];
    __syncthreads();
    if (tid < OUT_DIM) {
        float acc = 0.f;
        #pragma unroll 4
        for (int k = 0; k < HD; k++) acc += sm[k] * W[k * OUT_DIM + tid];
        out[b * OUT_DIM + tid] = acc + bb[tid];
    }
}

// ---------------- launch ----------------
extern "C" void kernel_launch(void* const* d_in, const int* in_sizes, int n_in,
                              void* d_out, int out_size) {
    const float* x     = (const float*)d_in[0];
    const int*   esrc  = (const int*)  d_in[1];
    const int*   edst  = (const int*)  d_in[2];
    const float* W_emb = (const float*)d_in[3];
    const float* b_emb = (const float*)d_in[4];
    const float* W_gcn = (const float*)d_in[5];
    const float* b_gcn = (const float*)d_in[6];
    const float* aW1   = (const float*)d_in[7];
    const float* ab1   = (const float*)d_in[8];
    const float* aW2   = (const float*)d_in[9];
    const float* ab2   = (const float*)d_in[10];
    const float* vW1   = (const float*)d_in[11];
    const float* vb1   = (const float*)d_in[12];
    const float* vW2   = (const float*)d_in[13];
    const float* vb2   = (const float*)d_in[14];
    const float* mW1   = (const float*)d_in[15];
    const float* mb1   = (const float*)d_in[16];
    const float* mW2   = (const float*)d_in[17];
    const float* mb2   = (const float*)d_in[18];
    const float* ew    = (const float*)d_in[19];
    float* out = (float*)d_out;

    float *d_dinv, *d_wc, *d_bc, *d_y, *d_sc, *d_g, *d_t1, *d_t, *d_proto, *d_pn,
          *d_ct, *d_vn, *d_vnr, *d_vn2, *d_gf, *d_m1;
    int *d_cnt, *d_csr;
    cudaGetSymbolAddress((void**)&d_cnt,   g_cnt);
    cudaGetSymbolAddress((void**)&d_dinv,  g_dinv);
    cudaGetSymbolAddress((void**)&d_csr,   g_csr);
    cudaGetSymbolAddress((void**)&d_wc,    g_wc);
    cudaGetSymbolAddress((void**)&d_bc,    g_bc);
    cudaGetSymbolAddress((void**)&d_y,     g_y);
    cudaGetSymbolAddress((void**)&d_sc,    g_sc);
    cudaGetSymbolAddress((void**)&d_g,     g_g);
    cudaGetSymbolAddress((void**)&d_t1,    g_t1);
    cudaGetSymbolAddress((void**)&d_t,     g_t);
    cudaGetSymbolAddress((void**)&d_proto, g_proto);
    cudaGetSymbolAddress((void**)&d_pn,    g_pn);
    cudaGetSymbolAddress((void**)&d_ct,    g_ct);
    cudaGetSymbolAddress((void**)&d_vn,    g_vn);
    cudaGetSymbolAddress((void**)&d_vnr,   g_vnr);
    cudaGetSymbolAddress((void**)&d_vn2,   g_vn2);
    cudaGetSymbolAddress((void**)&d_gf,    g_gf);
    cudaGetSymbolAddress((void**)&d_m1,    g_m1);

    // CSR build (counts double as degrees)
    cnt_zero_kernel<<<TOTAL_N / 256, 256>>>(d_cnt);
    csr_fill_kernel<<<EDGES / 256, 256>>>(esrc, edst, d_cnt, d_csr);
    dinv_kernel<<<TOTAL_N / 256, 256>>>(d_cnt, d_dinv);

    // weight fold (tiled): Wc = W_emb@W_gcn, bc = b_emb@W_gcn
    fold2_kernel<<<16, 256>>>(W_emb, b_emb, W_gcn, d_wc, d_bc);

    // sparse aggregation in x-space
    gcn_gather_x<<<TOTAL_N / 8, 256>>>(d_cnt, d_csr, d_dinv,
                                       (const float4*)x, (float4*)d_y, d_sc);

    // g = relu(y @ Wc + sc*bc + b_gcn)
    tf32x3_gemm<<<dim3(HD / TBN, TOTAL_N / TBM), 256>>>(
        d_y, d_wc, b_gcn, d_g, TOTAL_N, HD, IN_DIM, 1, 1, d_sc, d_bc, 1);

    // affinity MLP
    tf32x3_gemm<<<dim3(HD / TBN, TOTAL_N / TBM), 256>>>(
        d_g, aW1, ab1, d_t1, TOTAL_N, HD, HD, 1, 1, nullptr, nullptr, 0);
    tf32x3_gemm<<<dim3(HD / TBN, TOTAL_N / TBM), 256>>>(
        d_t1, aW2, ab2, d_t, TOTAL_N, HD, HD, 1, 0, nullptr, nullptr, 0);

    proto_pn_kernel<<<NB, HD>>>(d_t, d_proto, d_pn);
    att_mw_kernel<<<TOTAL_N / 8, 256>>>(d_t, d_proto, d_pn, ew, d_ct);

    // vn[b] = ct[b] @ g[b]  (batched tensor-core GEMM)
    vn_gemm<<<dim3(HD / TBN, 1, NB), 256>>>(d_ct, d_g, d_vn);

    // virtual-node MLP
    tf32x3_gemm<<<dim3(HD / TBN, (NB * NV) / TBM), 256>>>(
        d_vn, vW1, vb1, d_vnr, NB * NV, HD, HD, 1, 1, nullptr, nullptr, 0);
    tf32x3_gemm<<<dim3(HD / TBN, (NB * NV) / TBM), 256>>>(
        d_vnr, vW2, vb2, d_vn2, NB * NV, HD, HD, 1, 0, nullptr, nullptr, 0);

    gf_kernel<<<NB, HD>>>(d_vn2, d_gf);
    mlp1_kernel<<<NB, HD>>>(d_gf, mW1, mb1, d_m1);
    out_kernel<<<NB, HD>>>(d_m1, mW2, mb2, out);
}